// round 1
// baseline (speedup 1.0000x reference)
#include <cuda_runtime.h>
#include <cuda_bf16.h>

#define N_NODES 50000
#define E_EDGES 800000
#define EGT     200000

// ---------------- scratch (static device globals; no allocation) ----------------
__device__ float g_h0[N_NODES * 24];        // [x(16) | agg_trigger(4) | agg_action(4)]
__device__ int   g_degi[N_NODES];
__device__ int   g_cursor[N_NODES];
__device__ int   g_off[N_NODES + 1];
__device__ int   g_csrc[E_EDGES];           // src ids grouped by dst (CSR)
__device__ float g_agg24[N_NODES * 24];
__device__ float g_h1[N_NODES * 256];
__device__ float g_agg256[N_NODES * 256];
__device__ float g_h2[N_NODES * 128];
__device__ float g_uv[N_NODES * 256];       // [u(128) | v(128)] per node

// ---------------- init: h0 = [x | 0 | 0], zero counters ----------------
__global__ void k_init(const float* __restrict__ x) {
    int i = blockIdx.x * blockDim.x + threadIdx.x;
    if (i < N_NODES * 24) {
        int n = i / 24, c = i % 24;
        g_h0[i] = (c < 16) ? x[n * 16 + c] : 0.f;
    }
    if (i < N_NODES) { g_degi[i] = 0; g_cursor[i] = 0; }
}

// ---------------- edge-feature embedding scatter + degree count ----------------
__global__ void k_edge_feat(const int* __restrict__ ei, const int* __restrict__ ef,
                            const float* __restrict__ embT, const float* __restrict__ embA) {
    int e = blockIdx.x * blockDim.x + threadIdx.x;
    if (e >= E_EDGES) return;
    int s = ei[e], d = ei[E_EDGES + e];
    int t = ef[2 * e], a = ef[2 * e + 1];
#pragma unroll
    for (int k = 0; k < 4; k++) {
        atomicAdd(&g_h0[s * 24 + 16 + k], embT[t * 4 + k]);
        atomicAdd(&g_h0[d * 24 + 20 + k], embA[a * 4 + k]);
    }
    atomicAdd(&g_degi[d], 1);
}

// ---------------- single-block exclusive scan of degrees -> CSR offsets ----------------
__global__ void k_scan() {
    __shared__ int sh[1024];
    __shared__ int s_carry;
    int tid = threadIdx.x;
    if (tid == 0) s_carry = 0;
    for (int base = 0; base < N_NODES; base += 1024) {
        __syncthreads();
        int c0 = s_carry;
        int i = base + tid;
        int v = (i < N_NODES) ? g_degi[i] : 0;
        sh[tid] = v;
        __syncthreads();
        for (int ofs = 1; ofs < 1024; ofs <<= 1) {
            int t = (tid >= ofs) ? sh[tid - ofs] : 0;
            __syncthreads();
            sh[tid] += t;
            __syncthreads();
        }
        if (i < N_NODES) g_off[i] = c0 + sh[tid] - v;
        if (tid == 0) s_carry = c0 + sh[1023];
    }
    __syncthreads();
    if (tid == 0) g_off[N_NODES] = s_carry;
}

// ---------------- scatter src ids grouped by dst ----------------
__global__ void k_scatter(const int* __restrict__ ei) {
    int e = blockIdx.x * blockDim.x + threadIdx.x;
    if (e >= E_EDGES) return;
    int s = ei[e], d = ei[E_EDGES + e];
    int pos = g_off[d] + atomicAdd(&g_cursor[d], 1);
    g_csrc[pos] = s;
}

// ---------------- layer-1 aggregation in 24-dim space (warp per node) ----------------
__global__ void k_agg24() {
    int w = (blockIdx.x * blockDim.x + threadIdx.x) >> 5;
    int lane = threadIdx.x & 31;
    if (w >= N_NODES) return;
    int beg = g_off[w], end = g_off[w + 1];
    float acc = 0.f;
    if (lane < 24) {
        for (int e = beg; e < end; e++) {
            int s = g_csrc[e];
            acc += g_h0[s * 24 + lane];
        }
        float inv = 1.f / fmaxf((float)(end - beg), 1.f);
        g_agg24[w * 24 + lane] = acc * inv;
    }
}

// ---------------- GEMM1: h1 = relu([agg24|h0] @ [W1l;W1r] + b1), [N,48]@[48,256] ----------------
__global__ void k_gemm1(const float* __restrict__ W1l, const float* __restrict__ W1r,
                        const float* __restrict__ b1) {
    extern __shared__ float sm[];
    float* sW = sm;                                   // 48*256
    float (*sin)[48] = (float(*)[48])(sm + 48 * 256); // 4 rows
    int tid = threadIdx.x; // 256 = out col
    for (int i = tid; i < 24 * 256; i += 256) { sW[i] = W1l[i]; sW[24 * 256 + i] = W1r[i]; }
    float bias = b1[tid];
    __syncthreads();
    for (int r0 = blockIdx.x * 4; r0 < N_NODES; r0 += gridDim.x * 4) {
        for (int idx = tid; idx < 4 * 48; idx += 256) {
            int r = idx / 48, k = idx % 48;
            sin[r][k] = (k < 24) ? g_agg24[(r0 + r) * 24 + k] : g_h0[(r0 + r) * 24 + (k - 24)];
        }
        __syncthreads();
#pragma unroll
        for (int r = 0; r < 4; r++) {
            float acc = bias;
#pragma unroll
            for (int k = 0; k < 48; k += 4) {
                float4 s4 = *(float4*)&sin[r][k];
                acc += s4.x * sW[(k + 0) * 256 + tid] + s4.y * sW[(k + 1) * 256 + tid]
                     + s4.z * sW[(k + 2) * 256 + tid] + s4.w * sW[(k + 3) * 256 + tid];
            }
            g_h1[(r0 + r) * 256 + tid] = fmaxf(acc, 0.f);
        }
        __syncthreads();
    }
}

// ---------------- layer-2 aggregation: 256-dim gather-reduce (warp per node) ----------------
__global__ void k_agg256() {
    int w = (blockIdx.x * blockDim.x + threadIdx.x) >> 5;
    int lane = threadIdx.x & 31;
    if (w >= N_NODES) return;
    int beg = g_off[w], end = g_off[w + 1];
    float4 a0 = make_float4(0, 0, 0, 0), a1 = a0;
    for (int e = beg; e < end; e++) {
        int s = g_csrc[e];
        const float4* p = (const float4*)(g_h1 + (size_t)s * 256 + lane * 8);
        float4 x0 = p[0], x1 = p[1];
        a0.x += x0.x; a0.y += x0.y; a0.z += x0.z; a0.w += x0.w;
        a1.x += x1.x; a1.y += x1.y; a1.z += x1.z; a1.w += x1.w;
    }
    float inv = 1.f / fmaxf((float)(end - beg), 1.f);
    a0.x *= inv; a0.y *= inv; a0.z *= inv; a0.w *= inv;
    a1.x *= inv; a1.y *= inv; a1.z *= inv; a1.w *= inv;
    float4* q = (float4*)(g_agg256 + (size_t)w * 256 + lane * 8);
    q[0] = a0; q[1] = a1;
}

// ---------------- GEMM2: h2 = relu([agg256|h1] @ [W2l;W2r] + b2), [N,512]@[512,128] ----------------
__global__ void k_gemm2(const float* __restrict__ W2l, const float* __restrict__ W2r,
                        const float* __restrict__ b2) {
    extern __shared__ float sm[];
    float* sW = sm;                                    // 128x128 tile
    float (*sin)[128] = (float(*)[128])(sm + 128 * 128); // 16 rows x 128
    int tid = threadIdx.x; // 128 = out col
    int r0 = blockIdx.x * 16;
    float bias = b2[tid];
    float acc[16];
#pragma unroll
    for (int r = 0; r < 16; r++) acc[r] = bias;
    for (int kt = 0; kt < 4; kt++) {
        const float* Wsrc = (kt < 2) ? (W2l + kt * 128 * 128) : (W2r + (kt - 2) * 128 * 128);
        for (int i = tid; i < 128 * 128; i += 128) sW[i] = Wsrc[i];
        const float* insrc = (kt < 2) ? g_agg256 : g_h1;
        int kofs = (kt & 1) * 128;
        for (int idx = tid; idx < 16 * 128; idx += 128) {
            int r = idx >> 7, k = idx & 127;
            sin[r][k] = insrc[(size_t)(r0 + r) * 256 + kofs + k];
        }
        __syncthreads();
        for (int k = 0; k < 128; k += 4) {
            float w0 = sW[(k + 0) * 128 + tid];
            float w1 = sW[(k + 1) * 128 + tid];
            float w2 = sW[(k + 2) * 128 + tid];
            float w3 = sW[(k + 3) * 128 + tid];
#pragma unroll
            for (int r = 0; r < 16; r++) {
                float4 s4 = *(float4*)&sin[r][k];
                acc[r] += s4.x * w0 + s4.y * w1 + s4.z * w2 + s4.w * w3;
            }
        }
        __syncthreads();
    }
#pragma unroll
    for (int r = 0; r < 16; r++)
        g_h2[(size_t)(r0 + r) * 128 + tid] = fmaxf(acc[r], 0.f);
}

// ---------------- per-node classifier split: uv = h2 @ [Wc1_top | Wc1_bot], [N,128]@[128,256] ----------------
__global__ void k_uv(const float* __restrict__ Wc1) {
    extern __shared__ float sm[];
    float* sW = sm;                                     // 128x256
    float (*sin)[128] = (float(*)[128])(sm + 128 * 256); // 8 rows
    int tid = threadIdx.x; // 256 = out col (u: 0..127, v: 128..255)
    for (int i = tid; i < 128 * 256; i += 256) {
        int k = i >> 8, c = i & 255;
        sW[i] = (c < 128) ? Wc1[k * 128 + c] : Wc1[(128 + k) * 128 + (c - 128)];
    }
    __syncthreads();
    for (int r0 = blockIdx.x * 8; r0 < N_NODES; r0 += gridDim.x * 8) {
        for (int idx = tid; idx < 8 * 128; idx += 256) {
            int r = idx >> 7, k = idx & 127;
            sin[r][k] = g_h2[(size_t)(r0 + r) * 128 + k];
        }
        __syncthreads();
        float acc[8];
#pragma unroll
        for (int r = 0; r < 8; r++) acc[r] = 0.f;
        for (int k = 0; k < 128; k += 4) {
            float w0 = sW[(k + 0) * 256 + tid];
            float w1 = sW[(k + 1) * 256 + tid];
            float w2 = sW[(k + 2) * 256 + tid];
            float w3 = sW[(k + 3) * 256 + tid];
#pragma unroll
            for (int r = 0; r < 8; r++) {
                float4 s4 = *(float4*)&sin[r][k];
                acc[r] += s4.x * w0 + s4.y * w1 + s4.z * w2 + s4.w * w3;
            }
        }
#pragma unroll
        for (int r = 0; r < 8; r++)
            g_uv[(size_t)(r0 + r) * 256 + tid] = acc[r];
        __syncthreads();
    }
}

// ---------------- edge classifier: z = relu(u[s]+v[d]+bc1); out = sigmoid(z @ Wc2 + bc2) ----------------
#define R_E 32
__global__ void k_edge(const int* __restrict__ egt, const float* __restrict__ bc1,
                       const float* __restrict__ Wc2, const float* __restrict__ bc2,
                       float* __restrict__ out) {
    __shared__ float z[R_E][128];
    __shared__ int ss[R_E], dd[R_E];
    int tid = threadIdx.x; // 552 = out col
    int e0 = blockIdx.x * R_E;
    if (tid < R_E) { ss[tid] = egt[e0 + tid]; dd[tid] = egt[EGT + e0 + tid]; }
    __syncthreads();
    for (int idx = tid; idx < R_E * 128; idx += 552) {
        int r = idx >> 7, k = idx & 127;
        float val = g_uv[(size_t)ss[r] * 256 + k] + g_uv[(size_t)dd[r] * 256 + 128 + k] + bc1[k];
        z[r][k] = fmaxf(val, 0.f);
    }
    __syncthreads();
    float bias = bc2[tid];
    float acc[R_E];
#pragma unroll
    for (int r = 0; r < R_E; r++) acc[r] = bias;
    for (int k = 0; k < 128; k += 4) {
        float w0 = Wc2[(k + 0) * 552 + tid];
        float w1 = Wc2[(k + 1) * 552 + tid];
        float w2 = Wc2[(k + 2) * 552 + tid];
        float w3 = Wc2[(k + 3) * 552 + tid];
#pragma unroll
        for (int r = 0; r < R_E; r++) {
            float4 zv = *(float4*)&z[r][k];
            acc[r] += zv.x * w0 + zv.y * w1 + zv.z * w2 + zv.w * w3;
        }
    }
#pragma unroll
    for (int r = 0; r < R_E; r++)
        out[(size_t)(e0 + r) * 552 + tid] = 1.f / (1.f + __expf(-acc[r]));
}

// ---------------- launch ----------------
extern "C" void kernel_launch(void* const* d_in, const int* in_sizes, int n_in,
                              void* d_out, int out_size) {
    const float* x    = (const float*)d_in[0];
    const int*   ei   = (const int*)  d_in[1];
    const int*   egt  = (const int*)  d_in[2];
    const int*   ef   = (const int*)  d_in[3];
    const float* embT = (const float*)d_in[4];
    const float* embA = (const float*)d_in[5];
    const float* W1l  = (const float*)d_in[6];
    const float* W1r  = (const float*)d_in[7];
    const float* b1   = (const float*)d_in[8];
    const float* W2l  = (const float*)d_in[9];
    const float* W2r  = (const float*)d_in[10];
    const float* b2   = (const float*)d_in[11];
    const float* Wc1  = (const float*)d_in[12];
    const float* bc1  = (const float*)d_in[13];
    const float* Wc2  = (const float*)d_in[14];
    const float* bc2  = (const float*)d_in[15];
    float* out = (float*)d_out;

    const int smem_g1 = 48 * 256 * 4 + 4 * 48 * 4;       // 49920
    const int smem_g2 = 128 * 128 * 4 + 16 * 128 * 4;    // 73728
    const int smem_uv = 128 * 256 * 4 + 8 * 128 * 4;     // 135168
    cudaFuncSetAttribute(k_gemm1, cudaFuncAttributeMaxDynamicSharedMemorySize, smem_g1);
    cudaFuncSetAttribute(k_gemm2, cudaFuncAttributeMaxDynamicSharedMemorySize, smem_g2);
    cudaFuncSetAttribute(k_uv,    cudaFuncAttributeMaxDynamicSharedMemorySize, smem_uv);

    k_init<<<(N_NODES * 24 + 255) / 256, 256>>>(x);
    k_edge_feat<<<(E_EDGES + 255) / 256, 256>>>(ei, ef, embT, embA);
    k_scan<<<1, 1024>>>();
    k_scatter<<<(E_EDGES + 255) / 256, 256>>>(ei);
    k_agg24<<<(N_NODES * 32 + 255) / 256, 256>>>();
    k_gemm1<<<512, 256, smem_g1>>>(W1l, W1r, b1);
    k_agg256<<<(N_NODES * 32 + 255) / 256, 256>>>();
    k_gemm2<<<N_NODES / 16, 128, smem_g2>>>(W2l, W2r, b2);
    k_uv<<<1024, 256, smem_uv>>>(Wc1);
    k_edge<<<EGT / R_E, 552>>>(egt, bc1, Wc2, bc2, out);
}

// round 3
// speedup vs baseline: 1.2711x; 1.2711x over previous
#include <cuda_runtime.h>
#include <cuda_bf16.h>
#include <cstdint>

#define N_NODES 50000
#define E_EDGES 800000
#define EGT     200000

// ---------------- scratch (static device globals; no allocation) ----------------
__device__ float g_h0[N_NODES * 24];        // [x(16) | agg_trigger(4) | agg_action(4)]
__device__ int   g_degi[N_NODES];
__device__ int   g_cursor[N_NODES];
__device__ int   g_off[N_NODES + 1];
__device__ int   g_csrc[E_EDGES];           // src ids grouped by dst (CSR)
__device__ float g_agg24[N_NODES * 24];
__device__ float g_h1[N_NODES * 256];
__device__ float g_agg256[N_NODES * 256];
__device__ float g_h2[N_NODES * 128];
__device__ float g_uv[N_NODES * 256];       // [u(128) | v(128)] per node
__device__ __nv_bfloat16 g_wc2h[552 * 128]; // Wc2^T hi, [n][k]
__device__ __nv_bfloat16 g_wc2l[552 * 128]; // Wc2^T lo, [n][k]

// ======================= warp-MMA helpers (baseline PTX, sm_80+) =======================
__device__ __forceinline__ uint32_t smem_u32(const void* p) {
    uint32_t a;
    asm("{ .reg .u64 t; cvta.to.shared.u64 t, %1; cvt.u32.u64 %0, t; }" : "=r"(a) : "l"(p));
    return a;
}
__device__ __forceinline__ void ldm_x4(uint32_t* r, uint32_t addr) {
    asm volatile("ldmatrix.sync.aligned.m8n8.x4.shared.b16 {%0,%1,%2,%3}, [%4];"
        : "=r"(r[0]), "=r"(r[1]), "=r"(r[2]), "=r"(r[3]) : "r"(addr));
}
__device__ __forceinline__ void mma_bf16(float* c, const uint32_t* a, const uint32_t* b) {
    asm volatile(
        "mma.sync.aligned.m16n8k16.row.col.f32.bf16.bf16.f32 "
        "{%0,%1,%2,%3}, {%4,%5,%6,%7}, {%8,%9}, {%0,%1,%2,%3};"
        : "+f"(c[0]), "+f"(c[1]), "+f"(c[2]), "+f"(c[3])
        : "r"(a[0]), "r"(a[1]), "r"(a[2]), "r"(a[3]), "r"(b[0]), "r"(b[1]));
}
__device__ __forceinline__ float sigf(float x) { return 1.f / (1.f + __expf(-x)); }

// ---------------- init: h0 = [x | 0 | 0], zero counters ----------------
__global__ void k_init(const float* __restrict__ x) {
    int i = blockIdx.x * blockDim.x + threadIdx.x;
    if (i < N_NODES * 24) {
        int n = i / 24, c = i % 24;
        g_h0[i] = (c < 16) ? x[n * 16 + c] : 0.f;
    }
    if (i < N_NODES) { g_degi[i] = 0; g_cursor[i] = 0; }
}

// ---------------- Wc2 -> bf16 hi/lo, transposed to [n][k] ----------------
__global__ void k_wc2_prep(const float* __restrict__ Wc2) {
    int i = blockIdx.x * blockDim.x + threadIdx.x;
    if (i >= 552 * 128) return;
    int n = i >> 7, k = i & 127;
    float w = Wc2[(size_t)k * 552 + n];
    __nv_bfloat16 h = __float2bfloat16(w);
    __nv_bfloat16 l = __float2bfloat16(w - __bfloat162float(h));
    g_wc2h[i] = h;
    g_wc2l[i] = l;
}

// ---------------- edge-feature embedding scatter + degree count ----------------
__global__ void k_edge_feat(const int* __restrict__ ei, const int* __restrict__ ef,
                            const float* __restrict__ embT, const float* __restrict__ embA) {
    int e = blockIdx.x * blockDim.x + threadIdx.x;
    if (e >= E_EDGES) return;
    int s = ei[e], d = ei[E_EDGES + e];
    int t = ef[2 * e], a = ef[2 * e + 1];
#pragma unroll
    for (int k = 0; k < 4; k++) {
        atomicAdd(&g_h0[s * 24 + 16 + k], embT[t * 4 + k]);
        atomicAdd(&g_h0[d * 24 + 20 + k], embA[a * 4 + k]);
    }
    atomicAdd(&g_degi[d], 1);
}

// ---------------- single-block exclusive scan of degrees -> CSR offsets ----------------
__global__ void k_scan() {
    __shared__ int sh[1024];
    __shared__ int s_carry;
    int tid = threadIdx.x;
    if (tid == 0) s_carry = 0;
    for (int base = 0; base < N_NODES; base += 1024) {
        __syncthreads();
        int c0 = s_carry;
        int i = base + tid;
        int v = (i < N_NODES) ? g_degi[i] : 0;
        sh[tid] = v;
        __syncthreads();
        for (int ofs = 1; ofs < 1024; ofs <<= 1) {
            int t = (tid >= ofs) ? sh[tid - ofs] : 0;
            __syncthreads();
            sh[tid] += t;
            __syncthreads();
        }
        if (i < N_NODES) g_off[i] = c0 + sh[tid] - v;
        if (tid == 0) s_carry = c0 + sh[1023];
    }
    __syncthreads();
    if (tid == 0) g_off[N_NODES] = s_carry;
}

// ---------------- scatter src ids grouped by dst ----------------
__global__ void k_scatter(const int* __restrict__ ei) {
    int e = blockIdx.x * blockDim.x + threadIdx.x;
    if (e >= E_EDGES) return;
    int s = ei[e], d = ei[E_EDGES + e];
    int pos = g_off[d] + atomicAdd(&g_cursor[d], 1);
    g_csrc[pos] = s;
}

// ---------------- layer-1 aggregation in 24-dim space (warp per node) ----------------
__global__ void k_agg24() {
    int w = (blockIdx.x * blockDim.x + threadIdx.x) >> 5;
    int lane = threadIdx.x & 31;
    if (w >= N_NODES) return;
    int beg = g_off[w], end = g_off[w + 1];
    float acc = 0.f;
    if (lane < 24) {
        for (int e = beg; e < end; e++) {
            int s = g_csrc[e];
            acc += g_h0[s * 24 + lane];
        }
        float inv = 1.f / fmaxf((float)(end - beg), 1.f);
        g_agg24[w * 24 + lane] = acc * inv;
    }
}

// ---------------- GEMM1: h1 = relu([agg24|h0] @ [W1l;W1r] + b1), [N,48]@[48,256] ----------------
__global__ void k_gemm1(const float* __restrict__ W1l, const float* __restrict__ W1r,
                        const float* __restrict__ b1) {
    extern __shared__ float sm[];
    float* sW = sm;                                   // 48*256
    float (*sin)[48] = (float(*)[48])(sm + 48 * 256); // 4 rows
    int tid = threadIdx.x; // 256 = out col
    for (int i = tid; i < 24 * 256; i += 256) { sW[i] = W1l[i]; sW[24 * 256 + i] = W1r[i]; }
    float bias = b1[tid];
    __syncthreads();
    for (int r0 = blockIdx.x * 4; r0 < N_NODES; r0 += gridDim.x * 4) {
        for (int idx = tid; idx < 4 * 48; idx += 256) {
            int r = idx / 48, k = idx % 48;
            sin[r][k] = (k < 24) ? g_agg24[(r0 + r) * 24 + k] : g_h0[(r0 + r) * 24 + (k - 24)];
        }
        __syncthreads();
#pragma unroll
        for (int r = 0; r < 4; r++) {
            float acc = bias;
#pragma unroll
            for (int k = 0; k < 48; k += 4) {
                float4 s4 = *(float4*)&sin[r][k];
                acc += s4.x * sW[(k + 0) * 256 + tid] + s4.y * sW[(k + 1) * 256 + tid]
                     + s4.z * sW[(k + 2) * 256 + tid] + s4.w * sW[(k + 3) * 256 + tid];
            }
            g_h1[(r0 + r) * 256 + tid] = fmaxf(acc, 0.f);
        }
        __syncthreads();
    }
}

// ---------------- layer-2 aggregation: 256-dim gather-reduce (warp per node) ----------------
__global__ void k_agg256() {
    int w = (blockIdx.x * blockDim.x + threadIdx.x) >> 5;
    int lane = threadIdx.x & 31;
    if (w >= N_NODES) return;
    int beg = g_off[w], end = g_off[w + 1];
    float4 a0 = make_float4(0, 0, 0, 0), a1 = a0;
    for (int e = beg; e < end; e++) {
        int s = g_csrc[e];
        const float4* p = (const float4*)(g_h1 + (size_t)s * 256 + lane * 8);
        float4 x0 = p[0], x1 = p[1];
        a0.x += x0.x; a0.y += x0.y; a0.z += x0.z; a0.w += x0.w;
        a1.x += x1.x; a1.y += x1.y; a1.z += x1.z; a1.w += x1.w;
    }
    float inv = 1.f / fmaxf((float)(end - beg), 1.f);
    a0.x *= inv; a0.y *= inv; a0.z *= inv; a0.w *= inv;
    a1.x *= inv; a1.y *= inv; a1.z *= inv; a1.w *= inv;
    float4* q = (float4*)(g_agg256 + (size_t)w * 256 + lane * 8);
    q[0] = a0; q[1] = a1;
}

// ---------------- GEMM2: h2 = relu([agg256|h1] @ [W2l;W2r] + b2), [N,512]@[512,128] ----------------
__global__ void k_gemm2(const float* __restrict__ W2l, const float* __restrict__ W2r,
                        const float* __restrict__ b2) {
    extern __shared__ float sm[];
    float* sW = sm;                                    // 128x128 tile
    float (*sin)[128] = (float(*)[128])(sm + 128 * 128); // 16 rows x 128
    int tid = threadIdx.x; // 128 = out col
    int r0 = blockIdx.x * 16;
    float bias = b2[tid];
    float acc[16];
#pragma unroll
    for (int r = 0; r < 16; r++) acc[r] = bias;
    for (int kt = 0; kt < 4; kt++) {
        const float* Wsrc = (kt < 2) ? (W2l + kt * 128 * 128) : (W2r + (kt - 2) * 128 * 128);
        for (int i = tid; i < 128 * 128; i += 128) sW[i] = Wsrc[i];
        const float* insrc = (kt < 2) ? g_agg256 : g_h1;
        int kofs = (kt & 1) * 128;
        for (int idx = tid; idx < 16 * 128; idx += 128) {
            int r = idx >> 7, k = idx & 127;
            sin[r][k] = insrc[(size_t)(r0 + r) * 256 + kofs + k];
        }
        __syncthreads();
        for (int k = 0; k < 128; k += 4) {
            float w0 = sW[(k + 0) * 128 + tid];
            float w1 = sW[(k + 1) * 128 + tid];
            float w2 = sW[(k + 2) * 128 + tid];
            float w3 = sW[(k + 3) * 128 + tid];
#pragma unroll
            for (int r = 0; r < 16; r++) {
                float4 s4 = *(float4*)&sin[r][k];
                acc[r] += s4.x * w0 + s4.y * w1 + s4.z * w2 + s4.w * w3;
            }
        }
        __syncthreads();
    }
#pragma unroll
    for (int r = 0; r < 16; r++)
        g_h2[(size_t)(r0 + r) * 128 + tid] = fmaxf(acc[r], 0.f);
}

// ---------------- per-node classifier split: uv = h2 @ [Wc1_top | Wc1_bot], [N,128]@[128,256] ----------------
__global__ void k_uv(const float* __restrict__ Wc1) {
    extern __shared__ float sm[];
    float* sW = sm;                                     // 128x256
    float (*sin)[128] = (float(*)[128])(sm + 128 * 256); // 8 rows
    int tid = threadIdx.x; // 256 = out col (u: 0..127, v: 128..255)
    for (int i = tid; i < 128 * 256; i += 256) {
        int k = i >> 8, c = i & 255;
        sW[i] = (c < 128) ? Wc1[k * 128 + c] : Wc1[(128 + k) * 128 + (c - 128)];
    }
    __syncthreads();
    for (int r0 = blockIdx.x * 8; r0 < N_NODES; r0 += gridDim.x * 8) {
        for (int idx = tid; idx < 8 * 128; idx += 256) {
            int r = idx >> 7, k = idx & 127;
            sin[r][k] = g_h2[(size_t)(r0 + r) * 128 + k];
        }
        __syncthreads();
        float acc[8];
#pragma unroll
        for (int r = 0; r < 8; r++) acc[r] = 0.f;
        for (int k = 0; k < 128; k += 4) {
            float w0 = sW[(k + 0) * 256 + tid];
            float w1 = sW[(k + 1) * 256 + tid];
            float w2 = sW[(k + 2) * 256 + tid];
            float w3 = sW[(k + 3) * 256 + tid];
#pragma unroll
            for (int r = 0; r < 8; r++) {
                float4 s4 = *(float4*)&sin[r][k];
                acc[r] += s4.x * w0 + s4.y * w1 + s4.z * w2 + s4.w * w3;
            }
        }
#pragma unroll
        for (int r = 0; r < 8; r++)
            g_uv[(size_t)(r0 + r) * 256 + tid] = acc[r];
        __syncthreads();
    }
}

// =====================================================================================
// k_edge_mma: edge classifier on mma.sync bf16 (hi/lo x3 split for fp32-class accuracy)
//   z[m,k]   = relu(u[s_m,k] + v[d_m,k] + bc1[k])       (M=128 edges/CTA, K=128)
//   out[m,c] = sigmoid(sum_k z[m,k]*Wc2[k,c] + bc2[c])   (N=552 = 3 chunks of 184)
// SMEM: A hi/lo (128x128 bf16 each), B hi/lo chunk (184x128 bf16 each).
// Row-major, 16B chunks XOR-swizzled: byte(r,c16) = r*256 + ((c16 ^ (r&7))<<4).
// =====================================================================================
#define EM_M     128
#define EM_NCH   184
#define EM_NT    23      // n-tiles (of 8) per chunk
#define SM_AH    0
#define SM_AL    32768
#define SM_BH    65536
#define SM_BL    112640
#define SM_EDGE_TOTAL 159744

__global__ __launch_bounds__(256, 1)
void k_edge_mma(const int* __restrict__ egt, const float* __restrict__ bc1,
                const float* __restrict__ bc2, float* __restrict__ out) {
    extern __shared__ char smem[];
    uint32_t sb = smem_u32(smem);
    int tid = threadIdx.x, wid = tid >> 5, lane = tid & 31;
    int e0 = blockIdx.x * EM_M;

    // ---- A prep: z -> hi/lo bf16. thread = (row m=tid/2, 64-col half h=tid&1)
    {
        int m = tid >> 1, h = tid & 1;
        int er = e0 + m;
        int s = 0, d = 0;
        if (er < EGT) { s = egt[er]; d = egt[EGT + er]; }
        const float* up = g_uv + (size_t)s * 256 + h * 64;
        const float* vp = g_uv + (size_t)d * 256 + 128 + h * 64;
        const float* bp = bc1 + h * 64;
#pragma unroll
        for (int kk = 0; kk < 64; kk += 8) {
            float z[8];
#pragma unroll
            for (int j = 0; j < 8; j += 4) {
                float4 u4 = *(const float4*)(up + kk + j);
                float4 v4 = *(const float4*)(vp + kk + j);
                float4 b4 = *(const float4*)(bp + kk + j);
                z[j + 0] = fmaxf(u4.x + v4.x + b4.x, 0.f);
                z[j + 1] = fmaxf(u4.y + v4.y + b4.y, 0.f);
                z[j + 2] = fmaxf(u4.z + v4.z + b4.z, 0.f);
                z[j + 3] = fmaxf(u4.w + v4.w + b4.w, 0.f);
            }
            uint32_t hw[4], lw[4];
#pragma unroll
            for (int p = 0; p < 4; p++) {
                __nv_bfloat16 h0 = __float2bfloat16(z[2 * p]);
                __nv_bfloat16 h1 = __float2bfloat16(z[2 * p + 1]);
                __nv_bfloat16 l0 = __float2bfloat16(z[2 * p] - __bfloat162float(h0));
                __nv_bfloat16 l1 = __float2bfloat16(z[2 * p + 1] - __bfloat162float(h1));
                __nv_bfloat162 hh = {h0, h1}, ll = {l0, l1};
                hw[p] = *reinterpret_cast<uint32_t*>(&hh);
                lw[p] = *reinterpret_cast<uint32_t*>(&ll);
            }
            int chunk = h * 8 + (kk >> 3);
            uint32_t off = (uint32_t)m * 256 + (uint32_t)((chunk ^ (m & 7)) << 4);
            *(uint4*)(smem + SM_AH + off) = make_uint4(hw[0], hw[1], hw[2], hw[3]);
            *(uint4*)(smem + SM_AL + off) = make_uint4(lw[0], lw[1], lw[2], lw[3]);
        }
    }
    __syncthreads();

    // ---- A fragments: warp wid owns rows [wid*16, wid*16+16). 8 ksteps x 4 regs, hi+lo.
    uint32_t Ah[32], Al[32];
    {
        int rowA = wid * 16 + (lane & 15);
        uint32_t rbase = (uint32_t)rowA * 256;
        int rx = rowA & 7;
        int csel = lane >> 4;   // 0: k-lo half of kstep, 1: k-hi half
#pragma unroll
        for (int ks = 0; ks < 8; ks++) {
            int chunk = ks * 2 + csel;
            uint32_t addr = sb + rbase + (uint32_t)((chunk ^ rx) << 4);
            ldm_x4(&Ah[ks * 4], addr + SM_AH);
            ldm_x4(&Al[ks * 4], addr + SM_AL);
        }
    }

    for (int ch = 0; ch < 3; ch++) {
        if (ch) __syncthreads();   // all warps done reading previous B chunk
        // ---- cooperative B chunk load (184 rows x 16 chunks of 16B), swizzled store
        {
            int nbase = ch * EM_NCH;
            for (int id = tid; id < EM_NCH * 16; id += 256) {
                int n = id >> 4, c = id & 15;
                uint32_t dst = (uint32_t)n * 256 + (uint32_t)((c ^ (n & 7)) << 4);
                *(uint4*)(smem + SM_BH + dst) = *(const uint4*)(g_wc2h + (size_t)(nbase + n) * 128 + c * 8);
                *(uint4*)(smem + SM_BL + dst) = *(const uint4*)(g_wc2l + (size_t)(nbase + n) * 128 + c * 8);
            }
        }
        __syncthreads();

        // ---- per warp: 23 n-tiles, each 24 HMMA (AhBh + AhBl + AlBh)
        int r0g = e0 + wid * 16 + (lane >> 2);
        bool v0 = r0g < EGT, v1 = (r0g + 8) < EGT;
        float* orow0 = out + (size_t)r0g * 552;
        float* orow1 = orow0 + 8 * 552;

        for (int nt = 0; nt < EM_NT; nt++) {
            uint32_t Bh[16], Bl[16];
            {
                int nrow = nt * 8 + (lane & 7);
                uint32_t rbase = (uint32_t)nrow * 256;
                int rx = nrow & 7;
                int csel = lane >> 3;   // 0..3
#pragma unroll
                for (int kp = 0; kp < 4; kp++) {
                    int chunk = kp * 4 + csel;
                    uint32_t addr = sb + rbase + (uint32_t)((chunk ^ rx) << 4);
                    ldm_x4(&Bh[kp * 4], addr + SM_BH);
                    ldm_x4(&Bl[kp * 4], addr + SM_BL);
                }
            }
            float accE[4] = {0, 0, 0, 0}, accO[4] = {0, 0, 0, 0};
#pragma unroll
            for (int ks = 0; ks < 8; ks++)
                mma_bf16((ks & 1) ? accO : accE, &Ah[ks * 4], &Bh[ks * 2]);
#pragma unroll
            for (int ks = 0; ks < 8; ks++)
                mma_bf16((ks & 1) ? accO : accE, &Ah[ks * 4], &Bl[ks * 2]);
#pragma unroll
            for (int ks = 0; ks < 8; ks++)
                mma_bf16((ks & 1) ? accO : accE, &Al[ks * 4], &Bh[ks * 2]);

            int col = ch * EM_NCH + nt * 8 + ((lane & 3) << 1);
            float bx = bc2[col], by = bc2[col + 1];
            if (v0) {
                float2 o0;
                o0.x = sigf(accE[0] + accO[0] + bx);
                o0.y = sigf(accE[1] + accO[1] + by);
                *(float2*)(orow0 + col) = o0;
            }
            if (v1) {
                float2 o1;
                o1.x = sigf(accE[2] + accO[2] + bx);
                o1.y = sigf(accE[3] + accO[3] + by);
                *(float2*)(orow1 + col) = o1;
            }
        }
    }
}

// ---------------- launch ----------------
extern "C" void kernel_launch(void* const* d_in, const int* in_sizes, int n_in,
                              void* d_out, int out_size) {
    const float* x    = (const float*)d_in[0];
    const int*   ei   = (const int*)  d_in[1];
    const int*   egt  = (const int*)  d_in[2];
    const int*   ef   = (const int*)  d_in[3];
    const float* embT = (const float*)d_in[4];
    const float* embA = (const float*)d_in[5];
    const float* W1l  = (const float*)d_in[6];
    const float* W1r  = (const float*)d_in[7];
    const float* b1   = (const float*)d_in[8];
    const float* W2l  = (const float*)d_in[9];
    const float* W2r  = (const float*)d_in[10];
    const float* b2   = (const float*)d_in[11];
    const float* Wc1  = (const float*)d_in[12];
    const float* bc1  = (const float*)d_in[13];
    const float* Wc2  = (const float*)d_in[14];
    const float* bc2  = (const float*)d_in[15];
    float* out = (float*)d_out;

    const int smem_g1 = 48 * 256 * 4 + 4 * 48 * 4;       // 49920
    const int smem_g2 = 128 * 128 * 4 + 16 * 128 * 4;    // 73728
    const int smem_uv = 128 * 256 * 4 + 8 * 128 * 4;     // 135168
    cudaFuncSetAttribute(k_gemm1, cudaFuncAttributeMaxDynamicSharedMemorySize, smem_g1);
    cudaFuncSetAttribute(k_gemm2, cudaFuncAttributeMaxDynamicSharedMemorySize, smem_g2);
    cudaFuncSetAttribute(k_uv,    cudaFuncAttributeMaxDynamicSharedMemorySize, smem_uv);
    cudaFuncSetAttribute(k_edge_mma, cudaFuncAttributeMaxDynamicSharedMemorySize, SM_EDGE_TOTAL);

    k_init<<<(N_NODES * 24 + 255) / 256, 256>>>(x);
    k_wc2_prep<<<(552 * 128 + 255) / 256, 256>>>(Wc2);
    k_edge_feat<<<(E_EDGES + 255) / 256, 256>>>(ei, ef, embT, embA);
    k_scan<<<1, 1024>>>();
    k_scatter<<<(E_EDGES + 255) / 256, 256>>>(ei);
    k_agg24<<<(N_NODES * 32 + 255) / 256, 256>>>();
    k_gemm1<<<512, 256, smem_g1>>>(W1l, W1r, b1);
    k_agg256<<<(N_NODES * 32 + 255) / 256, 256>>>();
    k_gemm2<<<N_NODES / 16, 128, smem_g2>>>(W2l, W2r, b2);
    k_uv<<<1024, 256, smem_uv>>>(Wc1);
    k_edge_mma<<<(EGT + EM_M - 1) / EM_M, 256, SM_EDGE_TOTAL>>>(egt, bc1, bc2, out);
}

// round 4
// speedup vs baseline: 1.9075x; 1.5006x over previous
#include <cuda_runtime.h>
#include <cuda_bf16.h>
#include <cstdint>

#define N_NODES 50000
#define E_EDGES 800000
#define EGT     200000

// ---------------- scratch (static device globals; no allocation) ----------------
__device__ float g_h0[N_NODES * 24];        // [x(16) | agg_trigger(4) | agg_action(4)]
__device__ int   g_degi[N_NODES];
__device__ int   g_cursor[N_NODES];
__device__ int   g_off[N_NODES + 1];
__device__ int   g_csrc[E_EDGES];           // src ids grouped by dst (CSR)
__device__ float g_agg24[N_NODES * 24];
__device__ float g_h1[N_NODES * 256];
__device__ float g_agg256[N_NODES * 256];
__device__ float g_h2[N_NODES * 128];
__device__ float g_uv[N_NODES * 256];       // [u(128) | v(128)] per node
__device__ __nv_bfloat16 g_wc2h[552 * 128]; // Wc2^T hi, [n][k]
__device__ __nv_bfloat16 g_wc2l[552 * 128]; // Wc2^T lo, [n][k]
__device__ __nv_bfloat16 g_w2h[128 * 512];  // [W2l;W2r]^T hi, [n][k] (k<256: W2l, else W2r)
__device__ __nv_bfloat16 g_w2l[128 * 512];
__device__ __nv_bfloat16 g_wuvh[256 * 128]; // [Wc1_top|Wc1_bot]^T hi, [n][k]
__device__ __nv_bfloat16 g_wuvl[256 * 128];

// ======================= warp-MMA helpers (baseline PTX, sm_80+) =======================
__device__ __forceinline__ uint32_t smem_u32(const void* p) {
    uint32_t a;
    asm("{ .reg .u64 t; cvta.to.shared.u64 t, %1; cvt.u32.u64 %0, t; }" : "=r"(a) : "l"(p));
    return a;
}
__device__ __forceinline__ void ldm_x4(uint32_t* r, uint32_t addr) {
    asm volatile("ldmatrix.sync.aligned.m8n8.x4.shared.b16 {%0,%1,%2,%3}, [%4];"
        : "=r"(r[0]), "=r"(r[1]), "=r"(r[2]), "=r"(r[3]) : "r"(addr));
}
__device__ __forceinline__ void mma_bf16(float* c, const uint32_t* a, const uint32_t* b) {
    asm volatile(
        "mma.sync.aligned.m16n8k16.row.col.f32.bf16.bf16.f32 "
        "{%0,%1,%2,%3}, {%4,%5,%6,%7}, {%8,%9}, {%0,%1,%2,%3};"
        : "+f"(c[0]), "+f"(c[1]), "+f"(c[2]), "+f"(c[3])
        : "r"(a[0]), "r"(a[1]), "r"(a[2]), "r"(a[3]), "r"(b[0]), "r"(b[1]));
}
__device__ __forceinline__ float sigf(float x) { return 1.f / (1.f + __expf(-x)); }

// split fp32 -> (hi, lo) bf16 pair words from 8 consecutive floats
__device__ __forceinline__ void split8(const float* z, uint32_t* hw, uint32_t* lw) {
#pragma unroll
    for (int p = 0; p < 4; p++) {
        __nv_bfloat16 h0 = __float2bfloat16(z[2 * p]);
        __nv_bfloat16 h1 = __float2bfloat16(z[2 * p + 1]);
        __nv_bfloat16 l0 = __float2bfloat16(z[2 * p] - __bfloat162float(h0));
        __nv_bfloat16 l1 = __float2bfloat16(z[2 * p + 1] - __bfloat162float(h1));
        __nv_bfloat162 hh = {h0, h1}, ll = {l0, l1};
        hw[p] = *reinterpret_cast<uint32_t*>(&hh);
        lw[p] = *reinterpret_cast<uint32_t*>(&ll);
    }
}

// ---------------- init: h0 = [x | 0 | 0], zero counters ----------------
__global__ void k_init(const float* __restrict__ x) {
    int i = blockIdx.x * blockDim.x + threadIdx.x;
    if (i < N_NODES * 24) {
        int n = i / 24, c = i % 24;
        g_h0[i] = (c < 16) ? x[n * 16 + c] : 0.f;
    }
    if (i < N_NODES) { g_degi[i] = 0; g_cursor[i] = 0; }
}

// ---------------- weight prep: transpose + bf16 hi/lo split ----------------
__global__ void k_wc2_prep(const float* __restrict__ Wc2) {
    int i = blockIdx.x * blockDim.x + threadIdx.x;
    if (i >= 552 * 128) return;
    int n = i >> 7, k = i & 127;
    float w = Wc2[(size_t)k * 552 + n];
    __nv_bfloat16 h = __float2bfloat16(w);
    g_wc2h[i] = h;
    g_wc2l[i] = __float2bfloat16(w - __bfloat162float(h));
}
__global__ void k_w2_prep(const float* __restrict__ W2l, const float* __restrict__ W2r) {
    int i = blockIdx.x * blockDim.x + threadIdx.x;
    if (i >= 128 * 512) return;
    int n = i >> 9, k = i & 511;
    float w = (k < 256) ? W2l[(size_t)k * 128 + n] : W2r[(size_t)(k - 256) * 128 + n];
    __nv_bfloat16 h = __float2bfloat16(w);
    g_w2h[i] = h;
    g_w2l[i] = __float2bfloat16(w - __bfloat162float(h));
}
__global__ void k_wuv_prep(const float* __restrict__ Wc1) {
    int i = blockIdx.x * blockDim.x + threadIdx.x;
    if (i >= 256 * 128) return;
    int n = i >> 7, k = i & 127;
    float w = (n < 128) ? Wc1[(size_t)k * 128 + n] : Wc1[(size_t)(128 + k) * 128 + (n - 128)];
    __nv_bfloat16 h = __float2bfloat16(w);
    g_wuvh[i] = h;
    g_wuvl[i] = __float2bfloat16(w - __bfloat162float(h));
}

// ---------------- edge-feature embedding scatter + degree count ----------------
__global__ void k_edge_feat(const int* __restrict__ ei, const int* __restrict__ ef,
                            const float* __restrict__ embT, const float* __restrict__ embA) {
    int e = blockIdx.x * blockDim.x + threadIdx.x;
    if (e >= E_EDGES) return;
    int s = ei[e], d = ei[E_EDGES + e];
    int t = ef[2 * e], a = ef[2 * e + 1];
#pragma unroll
    for (int k = 0; k < 4; k++) {
        atomicAdd(&g_h0[s * 24 + 16 + k], embT[t * 4 + k]);
        atomicAdd(&g_h0[d * 24 + 20 + k], embA[a * 4 + k]);
    }
    atomicAdd(&g_degi[d], 1);
}

// ---------------- scan: chunk-per-thread + warp-shuffle block scan ----------------
__global__ void k_scan() {
    const int CH = (N_NODES + 1023) / 1024;  // 49
    int tid = threadIdx.x, lane = tid & 31, wid = tid >> 5;
    int beg = tid * CH, end = min(beg + CH, N_NODES);
    int sum = 0;
    for (int i = beg; i < end; i++) sum += g_degi[i];
    int v = sum;
#pragma unroll
    for (int o = 1; o < 32; o <<= 1) {
        int t = __shfl_up_sync(0xFFFFFFFFu, v, o);
        if (lane >= o) v += t;
    }
    __shared__ int wsum[32];
    if (lane == 31) wsum[wid] = v;
    __syncthreads();
    if (wid == 0) {
        int w = wsum[lane];
#pragma unroll
        for (int o = 1; o < 32; o <<= 1) {
            int t = __shfl_up_sync(0xFFFFFFFFu, w, o);
            if (lane >= o) w += t;
        }
        wsum[lane] = w;
    }
    __syncthreads();
    int base = v - sum + (wid ? wsum[wid - 1] : 0);
    for (int i = beg; i < end; i++) { g_off[i] = base; base += g_degi[i]; }
    if (tid == 1023) g_off[N_NODES] = base;
}

// ---------------- scatter src ids grouped by dst ----------------
__global__ void k_scatter(const int* __restrict__ ei) {
    int e = blockIdx.x * blockDim.x + threadIdx.x;
    if (e >= E_EDGES) return;
    int s = ei[e], d = ei[E_EDGES + e];
    int pos = g_off[d] + atomicAdd(&g_cursor[d], 1);
    g_csrc[pos] = s;
}

// ---------------- layer-1 aggregation in 24-dim space (warp per node) ----------------
__global__ void k_agg24() {
    int w = (blockIdx.x * blockDim.x + threadIdx.x) >> 5;
    int lane = threadIdx.x & 31;
    if (w >= N_NODES) return;
    int beg = g_off[w], end = g_off[w + 1];
    float acc = 0.f;
    if (lane < 24) {
        for (int e = beg; e < end; e++) {
            int s = g_csrc[e];
            acc += g_h0[s * 24 + lane];
        }
        float inv = 1.f / fmaxf((float)(end - beg), 1.f);
        g_agg24[w * 24 + lane] = acc * inv;
    }
}

// ---------------- GEMM1: h1 = relu([agg24|h0] @ [W1l;W1r] + b1), [N,48]@[48,256] ----------------
__global__ void k_gemm1(const float* __restrict__ W1l, const float* __restrict__ W1r,
                        const float* __restrict__ b1) {
    extern __shared__ float sm[];
    float* sW = sm;                                   // 48*256
    float (*sin)[48] = (float(*)[48])(sm + 48 * 256); // 4 rows
    int tid = threadIdx.x; // 256 = out col
    for (int i = tid; i < 24 * 256; i += 256) { sW[i] = W1l[i]; sW[24 * 256 + i] = W1r[i]; }
    float bias = b1[tid];
    __syncthreads();
    for (int r0 = blockIdx.x * 4; r0 < N_NODES; r0 += gridDim.x * 4) {
        for (int idx = tid; idx < 4 * 48; idx += 256) {
            int r = idx / 48, k = idx % 48;
            sin[r][k] = (k < 24) ? g_agg24[(r0 + r) * 24 + k] : g_h0[(r0 + r) * 24 + (k - 24)];
        }
        __syncthreads();
#pragma unroll
        for (int r = 0; r < 4; r++) {
            float acc = bias;
#pragma unroll
            for (int k = 0; k < 48; k += 4) {
                float4 s4 = *(float4*)&sin[r][k];
                acc += s4.x * sW[(k + 0) * 256 + tid] + s4.y * sW[(k + 1) * 256 + tid]
                     + s4.z * sW[(k + 2) * 256 + tid] + s4.w * sW[(k + 3) * 256 + tid];
            }
            g_h1[(r0 + r) * 256 + tid] = fmaxf(acc, 0.f);
        }
        __syncthreads();
    }
}

// ---------------- layer-2 aggregation: 256-dim gather-reduce (warp per node) ----------------
__global__ void k_agg256() {
    int w = (blockIdx.x * blockDim.x + threadIdx.x) >> 5;
    int lane = threadIdx.x & 31;
    if (w >= N_NODES) return;
    int beg = g_off[w], end = g_off[w + 1];
    float4 a0 = make_float4(0, 0, 0, 0), a1 = a0;
    for (int e = beg; e < end; e++) {
        int s = g_csrc[e];
        const float4* p = (const float4*)(g_h1 + (size_t)s * 256 + lane * 8);
        float4 x0 = p[0], x1 = p[1];
        a0.x += x0.x; a0.y += x0.y; a0.z += x0.z; a0.w += x0.w;
        a1.x += x1.x; a1.y += x1.y; a1.z += x1.z; a1.w += x1.w;
    }
    float inv = 1.f / fmaxf((float)(end - beg), 1.f);
    a0.x *= inv; a0.y *= inv; a0.z *= inv; a0.w *= inv;
    a1.x *= inv; a1.y *= inv; a1.z *= inv; a1.w *= inv;
    float4* q = (float4*)(g_agg256 + (size_t)w * 256 + lane * 8);
    q[0] = a0; q[1] = a1;
}

// =====================================================================================
// k_gemm2_mma: h2 = relu([agg256|h1] @ [W2l;W2r] + b2) via bf16x3 mma.sync
// CTA: 128 nodes x 128 outs, K=512 in 4 chunks of 128. 256 threads (8 warps x 16 rows).
// =====================================================================================
#define G2_SA_H 0
#define G2_SA_L 32768
#define G2_SB_H 65536
#define G2_SB_L 98304
#define G2_SMEM 131072

__global__ __launch_bounds__(256, 1)
void k_gemm2_mma(const float* __restrict__ b2) {
    extern __shared__ char smem[];
    uint32_t sb = smem_u32(smem);
    int tid = threadIdx.x, wid = tid >> 5, lane = tid & 31;
    int r0 = blockIdx.x * 128;

    float acc[16][4];
#pragma unroll
    for (int nt = 0; nt < 16; nt++)
#pragma unroll
        for (int j = 0; j < 4; j++) acc[nt][j] = 0.f;

    for (int kc = 0; kc < 4; kc++) {
        if (kc) __syncthreads();
        // A chunk: 128 rows x 128 k, fp32 -> hi/lo bf16 (thread = row tid/2, 64-k half tid&1)
        {
            int m = tid >> 1, h = tid & 1;
            int node = min(r0 + m, N_NODES - 1);
            const float* src = ((kc < 2) ? (g_agg256 + (size_t)node * 256 + kc * 128)
                                         : (g_h1 + (size_t)node * 256 + (kc - 2) * 128)) + h * 64;
#pragma unroll
            for (int kk = 0; kk < 64; kk += 8) {
                float z[8];
                *(float4*)(z) = *(const float4*)(src + kk);
                *(float4*)(z + 4) = *(const float4*)(src + kk + 4);
                uint32_t hw[4], lw[4];
                split8(z, hw, lw);
                int chunk = h * 8 + (kk >> 3);
                uint32_t off = (uint32_t)m * 256 + (uint32_t)((chunk ^ (m & 7)) << 4);
                *(uint4*)(smem + G2_SA_H + off) = make_uint4(hw[0], hw[1], hw[2], hw[3]);
                *(uint4*)(smem + G2_SA_L + off) = make_uint4(lw[0], lw[1], lw[2], lw[3]);
            }
        }
        // B chunk: 128 n-rows x 128 k from prepped [n][512]
        {
            int n = tid >> 1, h = tid & 1;
            const __nv_bfloat16* srcH = g_w2h + (size_t)n * 512 + kc * 128 + h * 64;
            const __nv_bfloat16* srcL = g_w2l + (size_t)n * 512 + kc * 128 + h * 64;
#pragma unroll
            for (int c = 0; c < 8; c++) {
                int chunk = h * 8 + c;
                uint32_t off = (uint32_t)n * 256 + (uint32_t)((chunk ^ (n & 7)) << 4);
                *(uint4*)(smem + G2_SB_H + off) = *(const uint4*)(srcH + c * 8);
                *(uint4*)(smem + G2_SB_L + off) = *(const uint4*)(srcL + c * 8);
            }
        }
        __syncthreads();

        // A fragments for this k-chunk
        uint32_t Ah[32], Al[32];
        {
            int rowA = wid * 16 + (lane & 15);
            uint32_t rbase = (uint32_t)rowA * 256;
            int rx = rowA & 7;
            int csel = lane >> 4;
#pragma unroll
            for (int ks = 0; ks < 8; ks++) {
                int chunk = ks * 2 + csel;
                uint32_t addr = sb + rbase + (uint32_t)((chunk ^ rx) << 4);
                ldm_x4(&Ah[ks * 4], addr + G2_SA_H);
                ldm_x4(&Al[ks * 4], addr + G2_SA_L);
            }
        }
#pragma unroll
        for (int nt = 0; nt < 16; nt++) {
            uint32_t Bh[16], Bl[16];
            {
                int nrow = nt * 8 + (lane & 7);
                uint32_t rbase = (uint32_t)nrow * 256;
                int rx = nrow & 7;
                int csel = lane >> 3;
#pragma unroll
                for (int kp = 0; kp < 4; kp++) {
                    int chunk = kp * 4 + csel;
                    uint32_t addr = sb + rbase + (uint32_t)((chunk ^ rx) << 4);
                    ldm_x4(&Bh[kp * 4], addr + G2_SB_H);
                    ldm_x4(&Bl[kp * 4], addr + G2_SB_L);
                }
            }
            float accE[4] = {0, 0, 0, 0}, accO[4] = {0, 0, 0, 0};
#pragma unroll
            for (int ks = 0; ks < 8; ks++)
                mma_bf16((ks & 1) ? accO : accE, &Ah[ks * 4], &Bh[ks * 2]);
#pragma unroll
            for (int ks = 0; ks < 8; ks++)
                mma_bf16((ks & 1) ? accO : accE, &Ah[ks * 4], &Bl[ks * 2]);
#pragma unroll
            for (int ks = 0; ks < 8; ks++)
                mma_bf16((ks & 1) ? accO : accE, &Al[ks * 4], &Bh[ks * 2]);
#pragma unroll
            for (int j = 0; j < 4; j++) acc[nt][j] += accE[j] + accO[j];
        }
    }

    // epilogue: relu + bias
    int row0 = r0 + wid * 16 + (lane >> 2);
    int row1 = row0 + 8;
#pragma unroll
    for (int nt = 0; nt < 16; nt++) {
        int col = nt * 8 + ((lane & 3) << 1);
        float bx = b2[col], by = b2[col + 1];
        if (row0 < N_NODES) {
            float2 o = {fmaxf(acc[nt][0] + bx, 0.f), fmaxf(acc[nt][1] + by, 0.f)};
            *(float2*)(g_h2 + (size_t)row0 * 128 + col) = o;
        }
        if (row1 < N_NODES) {
            float2 o = {fmaxf(acc[nt][2] + bx, 0.f), fmaxf(acc[nt][3] + by, 0.f)};
            *(float2*)(g_h2 + (size_t)row1 * 128 + col) = o;
        }
    }
}

// =====================================================================================
// k_uv_mma: uv = h2 @ [Wc1_top | Wc1_bot] via bf16x3 mma.sync
// CTA: 64 nodes x 256 outs, K=128. 256 threads; warp = (msub=wid&3 -> 16 rows, nhalf=wid>>2).
// =====================================================================================
#define UV_SA_H 0
#define UV_SA_L 16384
#define UV_SB_H 32768
#define UV_SB_L 98304
#define UV_SMEM 163840

__global__ __launch_bounds__(256, 1)
void k_uv_mma() {
    extern __shared__ char smem[];
    uint32_t sb = smem_u32(smem);
    int tid = threadIdx.x, wid = tid >> 5, lane = tid & 31;
    int r0 = blockIdx.x * 64;

    // A: 64 rows x 128 k (thread = row tid/4, 32-k quarter tid&3)
    {
        int m = tid >> 2, q = tid & 3;
        int node = min(r0 + m, N_NODES - 1);
        const float* src = g_h2 + (size_t)node * 128 + q * 32;
#pragma unroll
        for (int kk = 0; kk < 32; kk += 8) {
            float z[8];
            *(float4*)(z) = *(const float4*)(src + kk);
            *(float4*)(z + 4) = *(const float4*)(src + kk + 4);
            uint32_t hw[4], lw[4];
            split8(z, hw, lw);
            int chunk = q * 4 + (kk >> 3);
            uint32_t off = (uint32_t)m * 256 + (uint32_t)((chunk ^ (m & 7)) << 4);
            *(uint4*)(smem + UV_SA_H + off) = make_uint4(hw[0], hw[1], hw[2], hw[3]);
            *(uint4*)(smem + UV_SA_L + off) = make_uint4(lw[0], lw[1], lw[2], lw[3]);
        }
    }
    // B: 256 n-rows x 128 k (thread = n row, full row copy)
    {
        int n = tid;
        const __nv_bfloat16* srcH = g_wuvh + (size_t)n * 128;
        const __nv_bfloat16* srcL = g_wuvl + (size_t)n * 128;
#pragma unroll
        for (int c = 0; c < 16; c++) {
            uint32_t off = (uint32_t)n * 256 + (uint32_t)((c ^ (n & 7)) << 4);
            *(uint4*)(smem + UV_SB_H + off) = *(const uint4*)(srcH + c * 8);
            *(uint4*)(smem + UV_SB_L + off) = *(const uint4*)(srcL + c * 8);
        }
    }
    __syncthreads();

    int msub = wid & 3, nhalf = wid >> 2;
    uint32_t Ah[32], Al[32];
    {
        int rowA = msub * 16 + (lane & 15);
        uint32_t rbase = (uint32_t)rowA * 256;
        int rx = rowA & 7;
        int csel = lane >> 4;
#pragma unroll
        for (int ks = 0; ks < 8; ks++) {
            int chunk = ks * 2 + csel;
            uint32_t addr = sb + rbase + (uint32_t)((chunk ^ rx) << 4);
            ldm_x4(&Ah[ks * 4], addr + UV_SA_H);
            ldm_x4(&Al[ks * 4], addr + UV_SA_L);
        }
    }

    int row0 = r0 + msub * 16 + (lane >> 2);
    int row1 = row0 + 8;
#pragma unroll
    for (int nt = 0; nt < 16; nt++) {
        uint32_t Bh[16], Bl[16];
        {
            int nrow = nhalf * 128 + nt * 8 + (lane & 7);
            uint32_t rbase = (uint32_t)nrow * 256;
            int rx = nrow & 7;
            int csel = lane >> 3;
#pragma unroll
            for (int kp = 0; kp < 4; kp++) {
                int chunk = kp * 4 + csel;
                uint32_t addr = sb + rbase + (uint32_t)((chunk ^ rx) << 4);
                ldm_x4(&Bh[kp * 4], addr + UV_SB_H);
                ldm_x4(&Bl[kp * 4], addr + UV_SB_L);
            }
        }
        float accE[4] = {0, 0, 0, 0}, accO[4] = {0, 0, 0, 0};
#pragma unroll
        for (int ks = 0; ks < 8; ks++)
            mma_bf16((ks & 1) ? accO : accE, &Ah[ks * 4], &Bh[ks * 2]);
#pragma unroll
        for (int ks = 0; ks < 8; ks++)
            mma_bf16((ks & 1) ? accO : accE, &Ah[ks * 4], &Bl[ks * 2]);
#pragma unroll
        for (int ks = 0; ks < 8; ks++)
            mma_bf16((ks & 1) ? accO : accE, &Al[ks * 4], &Bh[ks * 2]);

        int col = nhalf * 128 + nt * 8 + ((lane & 3) << 1);
        if (row0 < N_NODES) {
            float2 o = {accE[0] + accO[0], accE[1] + accO[1]};
            *(float2*)(g_uv + (size_t)row0 * 256 + col) = o;
        }
        if (row1 < N_NODES) {
            float2 o = {accE[2] + accO[2], accE[3] + accO[3]};
            *(float2*)(g_uv + (size_t)row1 * 256 + col) = o;
        }
    }
}

// =====================================================================================
// k_edge_mma: edge classifier on mma.sync bf16 (hi/lo x3)
// =====================================================================================
#define EM_M     128
#define EM_NCH   184
#define EM_NT    23
#define SM_AH    0
#define SM_AL    32768
#define SM_BH    65536
#define SM_BL    112640
#define SM_EDGE_TOTAL 159744

__global__ __launch_bounds__(256, 1)
void k_edge_mma(const int* __restrict__ egt, const float* __restrict__ bc1,
                const float* __restrict__ bc2, float* __restrict__ out) {
    extern __shared__ char smem[];
    uint32_t sb = smem_u32(smem);
    int tid = threadIdx.x, wid = tid >> 5, lane = tid & 31;
    int e0 = blockIdx.x * EM_M;

    // A prep: z = relu(u[s]+v[d]+bc1) -> hi/lo bf16
    {
        int m = tid >> 1, h = tid & 1;
        int er = e0 + m;
        int s = 0, d = 0;
        if (er < EGT) { s = egt[er]; d = egt[EGT + er]; }
        const float* up = g_uv + (size_t)s * 256 + h * 64;
        const float* vp = g_uv + (size_t)d * 256 + 128 + h * 64;
        const float* bp = bc1 + h * 64;
#pragma unroll
        for (int kk = 0; kk < 64; kk += 8) {
            float z[8];
#pragma unroll
            for (int j = 0; j < 8; j += 4) {
                float4 u4 = *(const float4*)(up + kk + j);
                float4 v4 = *(const float4*)(vp + kk + j);
                float4 b4 = *(const float4*)(bp + kk + j);
                z[j + 0] = fmaxf(u4.x + v4.x + b4.x, 0.f);
                z[j + 1] = fmaxf(u4.y + v4.y + b4.y, 0.f);
                z[j + 2] = fmaxf(u4.z + v4.z + b4.z, 0.f);
                z[j + 3] = fmaxf(u4.w + v4.w + b4.w, 0.f);
            }
            uint32_t hw[4], lw[4];
            split8(z, hw, lw);
            int chunk = h * 8 + (kk >> 3);
            uint32_t off = (uint32_t)m * 256 + (uint32_t)((chunk ^ (m & 7)) << 4);
            *(uint4*)(smem + SM_AH + off) = make_uint4(hw[0], hw[1], hw[2], hw[3]);
            *(uint4*)(smem + SM_AL + off) = make_uint4(lw[0], lw[1], lw[2], lw[3]);
        }
    }
    __syncthreads();

    uint32_t Ah[32], Al[32];
    {
        int rowA = wid * 16 + (lane & 15);
        uint32_t rbase = (uint32_t)rowA * 256;
        int rx = rowA & 7;
        int csel = lane >> 4;
#pragma unroll
        for (int ks = 0; ks < 8; ks++) {
            int chunk = ks * 2 + csel;
            uint32_t addr = sb + rbase + (uint32_t)((chunk ^ rx) << 4);
            ldm_x4(&Ah[ks * 4], addr + SM_AH);
            ldm_x4(&Al[ks * 4], addr + SM_AL);
        }
    }

    for (int ch = 0; ch < 3; ch++) {
        if (ch) __syncthreads();
        {
            int nbase = ch * EM_NCH;
            for (int id = tid; id < EM_NCH * 16; id += 256) {
                int n = id >> 4, c = id & 15;
                uint32_t dst = (uint32_t)n * 256 + (uint32_t)((c ^ (n & 7)) << 4);
                *(uint4*)(smem + SM_BH + dst) = *(const uint4*)(g_wc2h + (size_t)(nbase + n) * 128 + c * 8);
                *(uint4*)(smem + SM_BL + dst) = *(const uint4*)(g_wc2l + (size_t)(nbase + n) * 128 + c * 8);
            }
        }
        __syncthreads();

        int r0g = e0 + wid * 16 + (lane >> 2);
        bool v0 = r0g < EGT, v1 = (r0g + 8) < EGT;
        float* orow0 = out + (size_t)r0g * 552;
        float* orow1 = orow0 + 8 * 552;

        for (int nt = 0; nt < EM_NT; nt++) {
            uint32_t Bh[16], Bl[16];
            {
                int nrow = nt * 8 + (lane & 7);
                uint32_t rbase = (uint32_t)nrow * 256;
                int rx = nrow & 7;
                int csel = lane >> 3;
#pragma unroll
                for (int kp = 0; kp < 4; kp++) {
                    int chunk = kp * 4 + csel;
                    uint32_t addr = sb + rbase + (uint32_t)((chunk ^ rx) << 4);
                    ldm_x4(&Bh[kp * 4], addr + SM_BH);
                    ldm_x4(&Bl[kp * 4], addr + SM_BL);
                }
            }
            float accE[4] = {0, 0, 0, 0}, accO[4] = {0, 0, 0, 0};
#pragma unroll
            for (int ks = 0; ks < 8; ks++)
                mma_bf16((ks & 1) ? accO : accE, &Ah[ks * 4], &Bh[ks * 2]);
#pragma unroll
            for (int ks = 0; ks < 8; ks++)
                mma_bf16((ks & 1) ? accO : accE, &Ah[ks * 4], &Bl[ks * 2]);
#pragma unroll
            for (int ks = 0; ks < 8; ks++)
                mma_bf16((ks & 1) ? accO : accE, &Al[ks * 4], &Bh[ks * 2]);

            int col = ch * EM_NCH + nt * 8 + ((lane & 3) << 1);
            float bx = bc2[col], by = bc2[col + 1];
            if (v0) {
                float2 o0 = {sigf(accE[0] + accO[0] + bx), sigf(accE[1] + accO[1] + by)};
                *(float2*)(orow0 + col) = o0;
            }
            if (v1) {
                float2 o1 = {sigf(accE[2] + accO[2] + bx), sigf(accE[3] + accO[3] + by)};
                *(float2*)(orow1 + col) = o1;
            }
        }
    }
}

// ---------------- launch ----------------
extern "C" void kernel_launch(void* const* d_in, const int* in_sizes, int n_in,
                              void* d_out, int out_size) {
    const float* x    = (const float*)d_in[0];
    const int*   ei   = (const int*)  d_in[1];
    const int*   egt  = (const int*)  d_in[2];
    const int*   ef   = (const int*)  d_in[3];
    const float* embT = (const float*)d_in[4];
    const float* embA = (const float*)d_in[5];
    const float* W1l  = (const float*)d_in[6];
    const float* W1r  = (const float*)d_in[7];
    const float* b1   = (const float*)d_in[8];
    const float* W2l  = (const float*)d_in[9];
    const float* W2r  = (const float*)d_in[10];
    const float* b2   = (const float*)d_in[11];
    const float* Wc1  = (const float*)d_in[12];
    const float* bc1  = (const float*)d_in[13];
    const float* Wc2  = (const float*)d_in[14];
    const float* bc2  = (const float*)d_in[15];
    float* out = (float*)d_out;

    const int smem_g1 = 48 * 256 * 4 + 4 * 48 * 4;
    cudaFuncSetAttribute(k_gemm1, cudaFuncAttributeMaxDynamicSharedMemorySize, smem_g1);
    cudaFuncSetAttribute(k_gemm2_mma, cudaFuncAttributeMaxDynamicSharedMemorySize, G2_SMEM);
    cudaFuncSetAttribute(k_uv_mma, cudaFuncAttributeMaxDynamicSharedMemorySize, UV_SMEM);
    cudaFuncSetAttribute(k_edge_mma, cudaFuncAttributeMaxDynamicSharedMemorySize, SM_EDGE_TOTAL);

    k_init<<<(N_NODES * 24 + 255) / 256, 256>>>(x);
    k_wc2_prep<<<(552 * 128 + 255) / 256, 256>>>(Wc2);
    k_w2_prep<<<(128 * 512 + 255) / 256, 256>>>(W2l, W2r);
    k_wuv_prep<<<(256 * 128 + 255) / 256, 256>>>(Wc1);
    k_edge_feat<<<(E_EDGES + 255) / 256, 256>>>(ei, ef, embT, embA);
    k_scan<<<1, 1024>>>();
    k_scatter<<<(E_EDGES + 255) / 256, 256>>>(ei);
    k_agg24<<<(N_NODES * 32 + 255) / 256, 256>>>();
    k_gemm1<<<512, 256, smem_g1>>>(W1l, W1r, b1);
    k_agg256<<<(N_NODES * 32 + 255) / 256, 256>>>();
    k_gemm2_mma<<<(N_NODES + 127) / 128, 256, G2_SMEM>>>(b2);
    k_uv_mma<<<(N_NODES + 63) / 64, 256, UV_SMEM>>>();
    k_edge_mma<<<(EGT + EM_M - 1) / EM_M, 256, SM_EDGE_TOTAL>>>(egt, bc1, bc2, out);
}

// round 5
// speedup vs baseline: 2.0137x; 1.0557x over previous
#include <cuda_runtime.h>
#include <cuda_bf16.h>
#include <cstdint>

#define N_NODES 50000
#define E_EDGES 800000
#define EGT     200000

// ---------------- scratch (static device globals; no allocation) ----------------
__device__ float g_h0[N_NODES * 24];        // [x(16) | agg_trigger(4) | agg_action(4)]
__device__ int   g_degi[N_NODES];
__device__ int   g_cursor[N_NODES];
__device__ int   g_off[N_NODES + 1];
__device__ int   g_csrc[E_EDGES];           // src ids grouped by dst (CSR)
__device__ float g_agg24[N_NODES * 24];
__device__ float g_h1[N_NODES * 256];
__device__ float g_agg256[N_NODES * 256];
__device__ float g_uv[N_NODES * 256];       // [u(128) | v(128)] per node
__device__ __nv_bfloat16 g_wc2h[552 * 128]; // Wc2^T hi, [n][k]
__device__ __nv_bfloat16 g_wc2l[552 * 128];
__device__ __nv_bfloat16 g_w2h[128 * 512];  // [W2l;W2r]^T hi, [n][k]
__device__ __nv_bfloat16 g_w2l[128 * 512];
__device__ __nv_bfloat16 g_wuvh[256 * 128]; // [Wc1_top|Wc1_bot]^T hi, [n][k]
__device__ __nv_bfloat16 g_wuvl[256 * 128];
__device__ __nv_bfloat16 g_w1h[256 * 64];   // [W1l;W1r]^T hi, [n][k], k padded 48->64
__device__ __nv_bfloat16 g_w1l[256 * 64];

// ======================= warp-MMA helpers (baseline PTX, sm_80+) =======================
__device__ __forceinline__ uint32_t smem_u32(const void* p) {
    uint32_t a;
    asm("{ .reg .u64 t; cvta.to.shared.u64 t, %1; cvt.u32.u64 %0, t; }" : "=r"(a) : "l"(p));
    return a;
}
__device__ __forceinline__ void ldm_x4(uint32_t* r, uint32_t addr) {
    asm volatile("ldmatrix.sync.aligned.m8n8.x4.shared.b16 {%0,%1,%2,%3}, [%4];"
        : "=r"(r[0]), "=r"(r[1]), "=r"(r[2]), "=r"(r[3]) : "r"(addr));
}
__device__ __forceinline__ void mma_bf16(float* c, const uint32_t* a, const uint32_t* b) {
    asm volatile(
        "mma.sync.aligned.m16n8k16.row.col.f32.bf16.bf16.f32 "
        "{%0,%1,%2,%3}, {%4,%5,%6,%7}, {%8,%9}, {%0,%1,%2,%3};"
        : "+f"(c[0]), "+f"(c[1]), "+f"(c[2]), "+f"(c[3])
        : "r"(a[0]), "r"(a[1]), "r"(a[2]), "r"(a[3]), "r"(b[0]), "r"(b[1]));
}
__device__ __forceinline__ float sigf(float x) { return 1.f / (1.f + __expf(-x)); }

__device__ __forceinline__ void split8(const float* z, uint32_t* hw, uint32_t* lw) {
#pragma unroll
    for (int p = 0; p < 4; p++) {
        __nv_bfloat16 h0 = __float2bfloat16(z[2 * p]);
        __nv_bfloat16 h1 = __float2bfloat16(z[2 * p + 1]);
        __nv_bfloat16 l0 = __float2bfloat16(z[2 * p] - __bfloat162float(h0));
        __nv_bfloat16 l1 = __float2bfloat16(z[2 * p + 1] - __bfloat162float(h1));
        __nv_bfloat162 hh = {h0, h1}, ll = {l0, l1};
        hw[p] = *reinterpret_cast<uint32_t*>(&hh);
        lw[p] = *reinterpret_cast<uint32_t*>(&ll);
    }
}
// split a pair of floats to packed hi/lo words
__device__ __forceinline__ void split2(float x, float y, uint32_t& hw, uint32_t& lw) {
    __nv_bfloat16 h0 = __float2bfloat16(x);
    __nv_bfloat16 h1 = __float2bfloat16(y);
    __nv_bfloat16 l0 = __float2bfloat16(x - __bfloat162float(h0));
    __nv_bfloat16 l1 = __float2bfloat16(y - __bfloat162float(h1));
    __nv_bfloat162 hh = {h0, h1}, ll = {l0, l1};
    hw = *reinterpret_cast<uint32_t*>(&hh);
    lw = *reinterpret_cast<uint32_t*>(&ll);
}

// ---------------- init: h0 = [x | 0 | 0], zero counters ----------------
__global__ void k_init(const float* __restrict__ x) {
    int i = blockIdx.x * blockDim.x + threadIdx.x;
    if (i < N_NODES * 24) {
        int n = i / 24, c = i % 24;
        g_h0[i] = (c < 16) ? x[n * 16 + c] : 0.f;
    }
    if (i < N_NODES) { g_degi[i] = 0; g_cursor[i] = 0; }
}

// ---------------- weight prep kernels ----------------
__global__ void k_wc2_prep(const float* __restrict__ Wc2) {
    int i = blockIdx.x * blockDim.x + threadIdx.x;
    if (i >= 552 * 128) return;
    int n = i >> 7, k = i & 127;
    float w = Wc2[(size_t)k * 552 + n];
    __nv_bfloat16 h = __float2bfloat16(w);
    g_wc2h[i] = h;
    g_wc2l[i] = __float2bfloat16(w - __bfloat162float(h));
}
__global__ void k_w2_prep(const float* __restrict__ W2l, const float* __restrict__ W2r) {
    int i = blockIdx.x * blockDim.x + threadIdx.x;
    if (i >= 128 * 512) return;
    int n = i >> 9, k = i & 511;
    float w = (k < 256) ? W2l[(size_t)k * 128 + n] : W2r[(size_t)(k - 256) * 128 + n];
    __nv_bfloat16 h = __float2bfloat16(w);
    g_w2h[i] = h;
    g_w2l[i] = __float2bfloat16(w - __bfloat162float(h));
}
__global__ void k_wuv_prep(const float* __restrict__ Wc1) {
    int i = blockIdx.x * blockDim.x + threadIdx.x;
    if (i >= 256 * 128) return;
    int n = i >> 7, k = i & 127;
    float w = (n < 128) ? Wc1[(size_t)k * 128 + n] : Wc1[(size_t)(128 + k) * 128 + (n - 128)];
    __nv_bfloat16 h = __float2bfloat16(w);
    g_wuvh[i] = h;
    g_wuvl[i] = __float2bfloat16(w - __bfloat162float(h));
}
__global__ void k_w1_prep(const float* __restrict__ W1l, const float* __restrict__ W1r) {
    int i = blockIdx.x * blockDim.x + threadIdx.x;
    if (i >= 256 * 64) return;
    int n = i >> 6, k = i & 63;
    float w = 0.f;
    if (k < 24) w = W1l[(size_t)k * 256 + n];
    else if (k < 48) w = W1r[(size_t)(k - 24) * 256 + n];
    __nv_bfloat16 h = __float2bfloat16(w);
    g_w1h[i] = h;
    g_w1l[i] = __float2bfloat16(w - __bfloat162float(h));
}

// ---------------- edge-feature embedding scatter + degree count ----------------
__global__ void k_edge_feat(const int* __restrict__ ei, const int* __restrict__ ef,
                            const float* __restrict__ embT, const float* __restrict__ embA) {
    int e = blockIdx.x * blockDim.x + threadIdx.x;
    if (e >= E_EDGES) return;
    int s = ei[e], d = ei[E_EDGES + e];
    int t = ef[2 * e], a = ef[2 * e + 1];
#pragma unroll
    for (int k = 0; k < 4; k++) {
        atomicAdd(&g_h0[s * 24 + 16 + k], embT[t * 4 + k]);
        atomicAdd(&g_h0[d * 24 + 20 + k], embA[a * 4 + k]);
    }
    atomicAdd(&g_degi[d], 1);
}

// ---------------- scan: chunk-per-thread + warp-shuffle block scan ----------------
__global__ void k_scan() {
    const int CH = (N_NODES + 1023) / 1024;
    int tid = threadIdx.x, lane = tid & 31, wid = tid >> 5;
    int beg = tid * CH, end = min(beg + CH, N_NODES);
    int sum = 0;
    for (int i = beg; i < end; i++) sum += g_degi[i];
    int v = sum;
#pragma unroll
    for (int o = 1; o < 32; o <<= 1) {
        int t = __shfl_up_sync(0xFFFFFFFFu, v, o);
        if (lane >= o) v += t;
    }
    __shared__ int wsum[32];
    if (lane == 31) wsum[wid] = v;
    __syncthreads();
    if (wid == 0) {
        int w = wsum[lane];
#pragma unroll
        for (int o = 1; o < 32; o <<= 1) {
            int t = __shfl_up_sync(0xFFFFFFFFu, w, o);
            if (lane >= o) w += t;
        }
        wsum[lane] = w;
    }
    __syncthreads();
    int base = v - sum + (wid ? wsum[wid - 1] : 0);
    for (int i = beg; i < end; i++) { g_off[i] = base; base += g_degi[i]; }
    if (tid == 1023) g_off[N_NODES] = base;
}

// ---------------- scatter src ids grouped by dst ----------------
__global__ void k_scatter(const int* __restrict__ ei) {
    int e = blockIdx.x * blockDim.x + threadIdx.x;
    if (e >= E_EDGES) return;
    int s = ei[e], d = ei[E_EDGES + e];
    int pos = g_off[d] + atomicAdd(&g_cursor[d], 1);
    g_csrc[pos] = s;
}

// ---------------- layer-1 aggregation in 24-dim space (warp per node) ----------------
__global__ void k_agg24() {
    int w = (blockIdx.x * blockDim.x + threadIdx.x) >> 5;
    int lane = threadIdx.x & 31;
    if (w >= N_NODES) return;
    int beg = g_off[w], end = g_off[w + 1];
    float acc = 0.f;
    if (lane < 24) {
        for (int e = beg; e < end; e++) {
            int s = g_csrc[e];
            acc += g_h0[s * 24 + lane];
        }
        float inv = 1.f / fmaxf((float)(end - beg), 1.f);
        g_agg24[w * 24 + lane] = acc * inv;
    }
}

// =====================================================================================
// k_gemm1_mma: h1 = relu([agg24|h0] @ [W1l;W1r] + b1) via bf16x3 mma.sync
// CTA: 128 nodes x 256 outs, K=64 (48 padded). 256 threads.
// =====================================================================================
#define G1_SA_H 0
#define G1_SA_L 16384
#define G1_SB_H 32768
#define G1_SB_L 65536
#define G1_SMEM 98304

__global__ __launch_bounds__(256, 1)
void k_gemm1_mma(const float* __restrict__ b1) {
    extern __shared__ char smem[];
    uint32_t sb = smem_u32(smem);
    int tid = threadIdx.x, wid = tid >> 5, lane = tid & 31;
    int r0 = blockIdx.x * 128;

    // A: 128 rows x 64 k (thread = row tid/2, 32-k half tid&1), row stride 128B
    {
        int m = tid >> 1, h = tid & 1;
        int node = min(r0 + m, N_NODES - 1);
        const float* a24 = g_agg24 + (size_t)node * 24;
        const float* h0p = g_h0 + (size_t)node * 24;
#pragma unroll
        for (int kk = 0; kk < 32; kk += 8) {
            float z[8];
#pragma unroll
            for (int j = 0; j < 8; j++) {
                int k = h * 32 + kk + j;
                z[j] = (k < 24) ? a24[k] : ((k < 48) ? h0p[k - 24] : 0.f);
            }
            uint32_t hw[4], lw[4];
            split8(z, hw, lw);
            int c = h * 4 + (kk >> 3);
            uint32_t off = (uint32_t)m * 128 + (uint32_t)((c ^ (m & 7)) << 4);
            *(uint4*)(smem + G1_SA_H + off) = make_uint4(hw[0], hw[1], hw[2], hw[3]);
            *(uint4*)(smem + G1_SA_L + off) = make_uint4(lw[0], lw[1], lw[2], lw[3]);
        }
    }
    // B: 256 n-rows x 64 k, row stride 128B (thread = n row)
    {
        int n = tid;
        const __nv_bfloat16* srcH = g_w1h + (size_t)n * 64;
        const __nv_bfloat16* srcL = g_w1l + (size_t)n * 64;
#pragma unroll
        for (int c = 0; c < 8; c++) {
            uint32_t off = (uint32_t)n * 128 + (uint32_t)((c ^ (n & 7)) << 4);
            *(uint4*)(smem + G1_SB_H + off) = *(const uint4*)(srcH + c * 8);
            *(uint4*)(smem + G1_SB_L + off) = *(const uint4*)(srcL + c * 8);
        }
    }
    __syncthreads();

    // A fragments: 4 ksteps
    uint32_t Ah[16], Al[16];
    {
        int rowA = wid * 16 + (lane & 15);
        uint32_t rbase = (uint32_t)rowA * 128;
        int rx = rowA & 7;
        int csel = lane >> 4;
#pragma unroll
        for (int ks = 0; ks < 4; ks++) {
            int c = ks * 2 + csel;
            uint32_t addr = sb + rbase + (uint32_t)((c ^ rx) << 4);
            ldm_x4(&Ah[ks * 4], addr + G1_SA_H);
            ldm_x4(&Al[ks * 4], addr + G1_SA_L);
        }
    }

    int row0 = r0 + wid * 16 + (lane >> 2);
    int row1 = row0 + 8;
#pragma unroll
    for (int nt = 0; nt < 32; nt++) {
        uint32_t Bh[8], Bl[8];
        {
            int nrow = nt * 8 + (lane & 7);
            uint32_t rbase = (uint32_t)nrow * 128;
            int rx = nrow & 7;
            int csel = lane >> 3;
#pragma unroll
            for (int kp = 0; kp < 2; kp++) {
                int c = kp * 4 + csel;
                uint32_t addr = sb + rbase + (uint32_t)((c ^ rx) << 4);
                ldm_x4(&Bh[kp * 4], addr + G1_SB_H);
                ldm_x4(&Bl[kp * 4], addr + G1_SB_L);
            }
        }
        float accE[4] = {0, 0, 0, 0}, accO[4] = {0, 0, 0, 0};
#pragma unroll
        for (int ks = 0; ks < 4; ks++)
            mma_bf16((ks & 1) ? accO : accE, &Ah[ks * 4], &Bh[ks * 2]);
#pragma unroll
        for (int ks = 0; ks < 4; ks++)
            mma_bf16((ks & 1) ? accO : accE, &Ah[ks * 4], &Bl[ks * 2]);
#pragma unroll
        for (int ks = 0; ks < 4; ks++)
            mma_bf16((ks & 1) ? accO : accE, &Al[ks * 4], &Bh[ks * 2]);

        int col = nt * 8 + ((lane & 3) << 1);
        float bx = b1[col], by = b1[col + 1];
        if (row0 < N_NODES) {
            float2 o = {fmaxf(accE[0] + accO[0] + bx, 0.f), fmaxf(accE[1] + accO[1] + by, 0.f)};
            *(float2*)(g_h1 + (size_t)row0 * 256 + col) = o;
        }
        if (row1 < N_NODES) {
            float2 o = {fmaxf(accE[2] + accO[2] + bx, 0.f), fmaxf(accE[3] + accO[3] + by, 0.f)};
            *(float2*)(g_h1 + (size_t)row1 * 256 + col) = o;
        }
    }
}

// ---------------- layer-2 aggregation: 256-dim gather-reduce (warp per node) ----------------
__global__ void k_agg256() {
    int w = (blockIdx.x * blockDim.x + threadIdx.x) >> 5;
    int lane = threadIdx.x & 31;
    if (w >= N_NODES) return;
    int beg = g_off[w], end = g_off[w + 1];
    float4 a0 = make_float4(0, 0, 0, 0), a1 = a0;
    for (int e = beg; e < end; e++) {
        int s = g_csrc[e];
        const float4* p = (const float4*)(g_h1 + (size_t)s * 256 + lane * 8);
        float4 x0 = p[0], x1 = p[1];
        a0.x += x0.x; a0.y += x0.y; a0.z += x0.z; a0.w += x0.w;
        a1.x += x1.x; a1.y += x1.y; a1.z += x1.z; a1.w += x1.w;
    }
    float inv = 1.f / fmaxf((float)(end - beg), 1.f);
    a0.x *= inv; a0.y *= inv; a0.z *= inv; a0.w *= inv;
    a1.x *= inv; a1.y *= inv; a1.z *= inv; a1.w *= inv;
    float4* q = (float4*)(g_agg256 + (size_t)w * 256 + lane * 8);
    q[0] = a0; q[1] = a1;
}

// =====================================================================================
// k_gemm2uv_mma: FUSED  h2 = relu([agg256|h1]@[W2l;W2r]+b2);  uv = h2 @ Wuv
// CTA: 128 nodes. Phase 1: K=512 -> h2 in regs. Phase 2: h2 -> smem bf16 hi/lo,
// then [128x128]@[128x256] -> g_uv. 256 threads.
// =====================================================================================
#define F_SA_H   0
#define F_SA_L   32768
#define F_SB_H   65536
#define F_SB_L   98304
#define F_A2_H   0
#define F_A2_L   32768
#define F_BUV_H  65536
#define F_BUV_L  131072
#define F_SMEM   196608

__global__ __launch_bounds__(256, 1)
void k_gemm2uv_mma(const float* __restrict__ b2) {
    extern __shared__ char smem[];
    uint32_t sb = smem_u32(smem);
    int tid = threadIdx.x, wid = tid >> 5, lane = tid & 31;
    int r0 = blockIdx.x * 128;

    float acc[16][4];
#pragma unroll
    for (int nt = 0; nt < 16; nt++)
#pragma unroll
        for (int j = 0; j < 4; j++) acc[nt][j] = 0.f;

    // ---------------- phase 1: h2 accumulation over K=512 ----------------
    for (int kc = 0; kc < 4; kc++) {
        if (kc) __syncthreads();
        {
            int m = tid >> 1, h = tid & 1;
            int node = min(r0 + m, N_NODES - 1);
            const float* src = ((kc < 2) ? (g_agg256 + (size_t)node * 256 + kc * 128)
                                         : (g_h1 + (size_t)node * 256 + (kc - 2) * 128)) + h * 64;
#pragma unroll
            for (int kk = 0; kk < 64; kk += 8) {
                float z[8];
                *(float4*)(z) = *(const float4*)(src + kk);
                *(float4*)(z + 4) = *(const float4*)(src + kk + 4);
                uint32_t hw[4], lw[4];
                split8(z, hw, lw);
                int chunk = h * 8 + (kk >> 3);
                uint32_t off = (uint32_t)m * 256 + (uint32_t)((chunk ^ (m & 7)) << 4);
                *(uint4*)(smem + F_SA_H + off) = make_uint4(hw[0], hw[1], hw[2], hw[3]);
                *(uint4*)(smem + F_SA_L + off) = make_uint4(lw[0], lw[1], lw[2], lw[3]);
            }
        }
        {
            int n = tid >> 1, h = tid & 1;
            const __nv_bfloat16* srcH = g_w2h + (size_t)n * 512 + kc * 128 + h * 64;
            const __nv_bfloat16* srcL = g_w2l + (size_t)n * 512 + kc * 128 + h * 64;
#pragma unroll
            for (int c = 0; c < 8; c++) {
                int chunk = h * 8 + c;
                uint32_t off = (uint32_t)n * 256 + (uint32_t)((chunk ^ (n & 7)) << 4);
                *(uint4*)(smem + F_SB_H + off) = *(const uint4*)(srcH + c * 8);
                *(uint4*)(smem + F_SB_L + off) = *(const uint4*)(srcL + c * 8);
            }
        }
        __syncthreads();

        uint32_t Ah[32], Al[32];
        {
            int rowA = wid * 16 + (lane & 15);
            uint32_t rbase = (uint32_t)rowA * 256;
            int rx = rowA & 7;
            int csel = lane >> 4;
#pragma unroll
            for (int ks = 0; ks < 8; ks++) {
                int chunk = ks * 2 + csel;
                uint32_t addr = sb + rbase + (uint32_t)((chunk ^ rx) << 4);
                ldm_x4(&Ah[ks * 4], addr + F_SA_H);
                ldm_x4(&Al[ks * 4], addr + F_SA_L);
            }
        }
#pragma unroll
        for (int nt = 0; nt < 16; nt++) {
            uint32_t Bh[16], Bl[16];
            {
                int nrow = nt * 8 + (lane & 7);
                uint32_t rbase = (uint32_t)nrow * 256;
                int rx = nrow & 7;
                int csel = lane >> 3;
#pragma unroll
                for (int kp = 0; kp < 4; kp++) {
                    int chunk = kp * 4 + csel;
                    uint32_t addr = sb + rbase + (uint32_t)((chunk ^ rx) << 4);
                    ldm_x4(&Bh[kp * 4], addr + F_SB_H);
                    ldm_x4(&Bl[kp * 4], addr + F_SB_L);
                }
            }
            float accE[4] = {0, 0, 0, 0}, accO[4] = {0, 0, 0, 0};
#pragma unroll
            for (int ks = 0; ks < 8; ks++)
                mma_bf16((ks & 1) ? accO : accE, &Ah[ks * 4], &Bh[ks * 2]);
#pragma unroll
            for (int ks = 0; ks < 8; ks++)
                mma_bf16((ks & 1) ? accO : accE, &Ah[ks * 4], &Bl[ks * 2]);
#pragma unroll
            for (int ks = 0; ks < 8; ks++)
                mma_bf16((ks & 1) ? accO : accE, &Al[ks * 4], &Bh[ks * 2]);
#pragma unroll
            for (int j = 0; j < 4; j++) acc[nt][j] += accE[j] + accO[j];
        }
    }
    __syncthreads();   // all warps done reading SA/SB before repurposing

    // ---------------- phase 2: h2 -> A2 smem (hi/lo), Buv load, GEMM -> g_uv ----------------
    // Buv cooperative load (256 n-rows x 128 k)
    {
        int n = tid;
        const __nv_bfloat16* srcH = g_wuvh + (size_t)n * 128;
        const __nv_bfloat16* srcL = g_wuvl + (size_t)n * 128;
#pragma unroll
        for (int c = 0; c < 16; c++) {
            uint32_t off = (uint32_t)n * 256 + (uint32_t)((c ^ (n & 7)) << 4);
            *(uint4*)(smem + F_BUV_H + off) = *(const uint4*)(srcH + c * 8);
            *(uint4*)(smem + F_BUV_L + off) = *(const uint4*)(srcL + c * 8);
        }
    }
    // h2 = relu(acc + b2) -> A2 smem, hi/lo, swizzled
    {
        int rloc0 = wid * 16 + (lane >> 2);
        int rloc1 = rloc0 + 8;
        int rx0 = rloc0 & 7, rx1 = rloc1 & 7;
#pragma unroll
        for (int nt = 0; nt < 16; nt++) {
            int c = nt * 8 + ((lane & 3) << 1);
            float bx = b2[c], by = b2[c + 1];
            float v0x = fmaxf(acc[nt][0] + bx, 0.f), v0y = fmaxf(acc[nt][1] + by, 0.f);
            float v1x = fmaxf(acc[nt][2] + bx, 0.f), v1y = fmaxf(acc[nt][3] + by, 0.f);
            uint32_t hw, lw;
            uint32_t base0 = (uint32_t)rloc0 * 256 + (uint32_t)((((c >> 3) ^ rx0)) << 4) + (uint32_t)(c & 7) * 2;
            split2(v0x, v0y, hw, lw);
            *(uint32_t*)(smem + F_A2_H + base0) = hw;
            *(uint32_t*)(smem + F_A2_L + base0) = lw;
            uint32_t base1 = (uint32_t)rloc1 * 256 + (uint32_t)((((c >> 3) ^ rx1)) << 4) + (uint32_t)(c & 7) * 2;
            split2(v1x, v1y, hw, lw);
            *(uint32_t*)(smem + F_A2_H + base1) = hw;
            *(uint32_t*)(smem + F_A2_L + base1) = lw;
        }
    }
    __syncthreads();

    uint32_t Ah[32], Al[32];
    {
        int rowA = wid * 16 + (lane & 15);
        uint32_t rbase = (uint32_t)rowA * 256;
        int rx = rowA & 7;
        int csel = lane >> 4;
#pragma unroll
        for (int ks = 0; ks < 8; ks++) {
            int chunk = ks * 2 + csel;
            uint32_t addr = sb + rbase + (uint32_t)((chunk ^ rx) << 4);
            ldm_x4(&Ah[ks * 4], addr + F_A2_H);
            ldm_x4(&Al[ks * 4], addr + F_A2_L);
        }
    }
    int row0 = r0 + wid * 16 + (lane >> 2);
    int row1 = row0 + 8;
#pragma unroll
    for (int nt = 0; nt < 32; nt++) {
        uint32_t Bh[16], Bl[16];
        {
            int nrow = nt * 8 + (lane & 7);
            uint32_t rbase = (uint32_t)nrow * 256;
            int rx = nrow & 7;
            int csel = lane >> 3;
#pragma unroll
            for (int kp = 0; kp < 4; kp++) {
                int chunk = kp * 4 + csel;
                uint32_t addr = sb + rbase + (uint32_t)((chunk ^ rx) << 4);
                ldm_x4(&Bh[kp * 4], addr + F_BUV_H);
                ldm_x4(&Bl[kp * 4], addr + F_BUV_L);
            }
        }
        float accE[4] = {0, 0, 0, 0}, accO[4] = {0, 0, 0, 0};
#pragma unroll
        for (int ks = 0; ks < 8; ks++)
            mma_bf16((ks & 1) ? accO : accE, &Ah[ks * 4], &Bh[ks * 2]);
#pragma unroll
        for (int ks = 0; ks < 8; ks++)
            mma_bf16((ks & 1) ? accO : accE, &Ah[ks * 4], &Bl[ks * 2]);
#pragma unroll
        for (int ks = 0; ks < 8; ks++)
            mma_bf16((ks & 1) ? accO : accE, &Al[ks * 4], &Bh[ks * 2]);

        int col = nt * 8 + ((lane & 3) << 1);
        if (row0 < N_NODES) {
            float2 o = {accE[0] + accO[0], accE[1] + accO[1]};
            *(float2*)(g_uv + (size_t)row0 * 256 + col) = o;
        }
        if (row1 < N_NODES) {
            float2 o = {accE[2] + accO[2], accE[3] + accO[3]};
            *(float2*)(g_uv + (size_t)row1 * 256 + col) = o;
        }
    }
}

// =====================================================================================
// k_edge_mma: edge classifier on mma.sync bf16 (hi/lo x3)
// =====================================================================================
#define EM_M     128
#define EM_NCH   184
#define EM_NT    23
#define SM_AH    0
#define SM_AL    32768
#define SM_BH    65536
#define SM_BL    112640
#define SM_EDGE_TOTAL 159744

__global__ __launch_bounds__(256, 1)
void k_edge_mma(const int* __restrict__ egt, const float* __restrict__ bc1,
                const float* __restrict__ bc2, float* __restrict__ out) {
    extern __shared__ char smem[];
    uint32_t sb = smem_u32(smem);
    int tid = threadIdx.x, wid = tid >> 5, lane = tid & 31;
    int e0 = blockIdx.x * EM_M;

    // A prep: z = relu(u[s]+v[d]+bc1) -> hi/lo bf16
    {
        int m = tid >> 1, h = tid & 1;
        int er = e0 + m;
        int s = 0, d = 0;
        if (er < EGT) { s = egt[er]; d = egt[EGT + er]; }
        const float* up = g_uv + (size_t)s * 256 + h * 64;
        const float* vp = g_uv + (size_t)d * 256 + 128 + h * 64;
        const float* bp = bc1 + h * 64;
#pragma unroll
        for (int kk = 0; kk < 64; kk += 8) {
            float z[8];
#pragma unroll
            for (int j = 0; j < 8; j += 4) {
                float4 u4 = *(const float4*)(up + kk + j);
                float4 v4 = *(const float4*)(vp + kk + j);
                float4 b4 = *(const float4*)(bp + kk + j);
                z[j + 0] = fmaxf(u4.x + v4.x + b4.x, 0.f);
                z[j + 1] = fmaxf(u4.y + v4.y + b4.y, 0.f);
                z[j + 2] = fmaxf(u4.z + v4.z + b4.z, 0.f);
                z[j + 3] = fmaxf(u4.w + v4.w + b4.w, 0.f);
            }
            uint32_t hw[4], lw[4];
            split8(z, hw, lw);
            int chunk = h * 8 + (kk >> 3);
            uint32_t off = (uint32_t)m * 256 + (uint32_t)((chunk ^ (m & 7)) << 4);
            *(uint4*)(smem + SM_AH + off) = make_uint4(hw[0], hw[1], hw[2], hw[3]);
            *(uint4*)(smem + SM_AL + off) = make_uint4(lw[0], lw[1], lw[2], lw[3]);
        }
    }
    // B chunk-0 load overlapped with A prep (independent smem regions)
    {
        for (int id = tid; id < EM_NCH * 16; id += 256) {
            int n = id >> 4, c = id & 15;
            uint32_t dst = (uint32_t)n * 256 + (uint32_t)((c ^ (n & 7)) << 4);
            *(uint4*)(smem + SM_BH + dst) = *(const uint4*)(g_wc2h + (size_t)n * 128 + c * 8);
            *(uint4*)(smem + SM_BL + dst) = *(const uint4*)(g_wc2l + (size_t)n * 128 + c * 8);
        }
    }
    __syncthreads();

    uint32_t Ah[32], Al[32];
    {
        int rowA = wid * 16 + (lane & 15);
        uint32_t rbase = (uint32_t)rowA * 256;
        int rx = rowA & 7;
        int csel = lane >> 4;
#pragma unroll
        for (int ks = 0; ks < 8; ks++) {
            int chunk = ks * 2 + csel;
            uint32_t addr = sb + rbase + (uint32_t)((chunk ^ rx) << 4);
            ldm_x4(&Ah[ks * 4], addr + SM_AH);
            ldm_x4(&Al[ks * 4], addr + SM_AL);
        }
    }

    int r0g = e0 + wid * 16 + (lane >> 2);
    bool v0 = r0g < EGT, v1 = (r0g + 8) < EGT;
    float* orow0 = out + (size_t)r0g * 552;
    float* orow1 = orow0 + 8 * 552;

    for (int ch = 0; ch < 3; ch++) {
        for (int nt = 0; nt < EM_NT; nt++) {
            uint32_t Bh[16], Bl[16];
            {
                int nrow = nt * 8 + (lane & 7);
                uint32_t rbase = (uint32_t)nrow * 256;
                int rx = nrow & 7;
                int csel = lane >> 3;
#pragma unroll
                for (int kp = 0; kp < 4; kp++) {
                    int chunk = kp * 4 + csel;
                    uint32_t addr = sb + rbase + (uint32_t)((chunk ^ rx) << 4);
                    ldm_x4(&Bh[kp * 4], addr + SM_BH);
                    ldm_x4(&Bl[kp * 4], addr + SM_BL);
                }
            }
            float accE[4] = {0, 0, 0, 0}, accO[4] = {0, 0, 0, 0};
#pragma unroll
            for (int ks = 0; ks < 8; ks++)
                mma_bf16((ks & 1) ? accO : accE, &Ah[ks * 4], &Bh[ks * 2]);
#pragma unroll
            for (int ks = 0; ks < 8; ks++)
                mma_bf16((ks & 1) ? accO : accE, &Ah[ks * 4], &Bl[ks * 2]);
#pragma unroll
            for (int ks = 0; ks < 8; ks++)
                mma_bf16((ks & 1) ? accO : accE, &Al[ks * 4], &Bh[ks * 2]);

            int col = ch * EM_NCH + nt * 8 + ((lane & 3) << 1);
            float bx = bc2[col], by = bc2[col + 1];
            if (v0) {
                float2 o0 = {sigf(accE[0] + accO[0] + bx), sigf(accE[1] + accO[1] + by)};
                *(float2*)(orow0 + col) = o0;
            }
            if (v1) {
                float2 o1 = {sigf(accE[2] + accO[2] + bx), sigf(accE[3] + accO[3] + by)};
                *(float2*)(orow1 + col) = o1;
            }
        }
        if (ch < 2) {
            __syncthreads();
            int nbase = (ch + 1) * EM_NCH;
            for (int id = tid; id < EM_NCH * 16; id += 256) {
                int n = id >> 4, c = id & 15;
                uint32_t dst = (uint32_t)n * 256 + (uint32_t)((c ^ (n & 7)) << 4);
                *(uint4*)(smem + SM_BH + dst) = *(const uint4*)(g_wc2h + (size_t)(nbase + n) * 128 + c * 8);
                *(uint4*)(smem + SM_BL + dst) = *(const uint4*)(g_wc2l + (size_t)(nbase + n) * 128 + c * 8);
            }
            __syncthreads();
        }
    }
}

// ---------------- launch ----------------
extern "C" void kernel_launch(void* const* d_in, const int* in_sizes, int n_in,
                              void* d_out, int out_size) {
    const float* x    = (const float*)d_in[0];
    const int*   ei   = (const int*)  d_in[1];
    const int*   egt  = (const int*)  d_in[2];
    const int*   ef   = (const int*)  d_in[3];
    const float* embT = (const float*)d_in[4];
    const float* embA = (const float*)d_in[5];
    const float* W1l  = (const float*)d_in[6];
    const float* W1r  = (const float*)d_in[7];
    const float* b1   = (const float*)d_in[8];
    const float* W2l  = (const float*)d_in[9];
    const float* W2r  = (const float*)d_in[10];
    const float* b2   = (const float*)d_in[11];
    const float* Wc1  = (const float*)d_in[12];
    const float* bc1  = (const float*)d_in[13];
    const float* Wc2  = (const float*)d_in[14];
    const float* bc2  = (const float*)d_in[15];
    float* out = (float*)d_out;

    cudaFuncSetAttribute(k_gemm1_mma, cudaFuncAttributeMaxDynamicSharedMemorySize, G1_SMEM);
    cudaFuncSetAttribute(k_gemm2uv_mma, cudaFuncAttributeMaxDynamicSharedMemorySize, F_SMEM);
    cudaFuncSetAttribute(k_edge_mma, cudaFuncAttributeMaxDynamicSharedMemorySize, SM_EDGE_TOTAL);

    k_init<<<(N_NODES * 24 + 255) / 256, 256>>>(x);
    k_wc2_prep<<<(552 * 128 + 255) / 256, 256>>>(Wc2);
    k_w2_prep<<<(128 * 512 + 255) / 256, 256>>>(W2l, W2r);
    k_wuv_prep<<<(256 * 128 + 255) / 256, 256>>>(Wc1);
    k_w1_prep<<<(256 * 64 + 255) / 256, 256>>>(W1l, W1r);
    k_edge_feat<<<(E_EDGES + 255) / 256, 256>>>(ei, ef, embT, embA);
    k_scan<<<1, 1024>>>();
    k_scatter<<<(E_EDGES + 255) / 256, 256>>>(ei);
    k_agg24<<<(N_NODES * 32 + 255) / 256, 256>>>();
    k_gemm1_mma<<<(N_NODES + 127) / 128, 256, G1_SMEM>>>(b1);
    k_agg256<<<(N_NODES * 32 + 255) / 256, 256>>>();
    k_gemm2uv_mma<<<(N_NODES + 127) / 128, 256, F_SMEM>>>(b2);
    k_edge_mma<<<(EGT + EM_M - 1) / EM_M, 256, SM_EDGE_TOTAL>>>(egt, bc1, bc2, out);
}